// round 13
// baseline (speedup 1.0000x reference)
#include <cuda_runtime.h>
#include <cuda_bf16.h>
#include <math.h>

// ---------------- problem constants ----------------
#define NNODES 325
#define BATCH  64
#define TSTEPS 12
#define HORIZON 12
#define UNITS  64
#define DIN    2
#define STRR   384               // UNIFORM row stride (floats) for ALL cells
#define XKSTR  (NNODES*STRR)
#define NTH    512
#define SPLIT  192               // rank0 rows [0,192), rank1 [192,325)
#define MAXE   2600
#define WPMAX  32768
#define MAXNNZ 110000

typedef unsigned long long ull;
typedef __nv_bfloat16 bf16;

// ---------------- device scratch (A basis = [x,h]; B basis = [x,rh]) ----------------
__device__ __align__(16) float g_xkA[BATCH*XKSTR];
__device__ __align__(16) bf16  g_xhA[BATCH*XKSTR];
__device__ __align__(16) bf16  g_xlA[BATCH*XKSTR];
__device__ __align__(16) float g_xkB[BATCH*XKSTR];
__device__ __align__(16) bf16  g_xhB[BATCH*XKSTR];
__device__ __align__(16) bf16  g_xlB[BATCH*XKSTR];
__device__ float g_h0[BATCH*NNODES*UNITS];
__device__ float g_h1[BATCH*NNODES*UNITS];
__device__ float g_u [BATCH*NNODES*UNITS];
__device__ float g_din[BATCH*NNODES];
__device__ int   g_rowptr[NNODES+1];
__device__ int   g_cols[MAXNNZ];
__device__ float g_vals[MAXNNZ];
__device__ unsigned g_wph[8][WPMAX];
__device__ unsigned g_wpl[8][WPMAX];
__device__ unsigned g_pbar[BATCH];

__global__ void init_pbar(){ if (threadIdx.x < BATCH) g_pbar[threadIdx.x] = 0u; }

// ---------------- helpers ----------------
__device__ __forceinline__ void bfsplit(float a, bf16 &h, bf16 &l){
    h = __float2bfloat16(a);
    l = __float2bfloat16(a - __bfloat162float(h));
}
__device__ __forceinline__ void mma16816(float* d, const unsigned* a, const unsigned* b){
    asm volatile("mma.sync.aligned.m16n8k16.row.col.f32.bf16.bf16.f32 "
        "{%0,%1,%2,%3}, {%4,%5,%6,%7}, {%8,%9}, {%0,%1,%2,%3};"
        : "+f"(d[0]), "+f"(d[1]), "+f"(d[2]), "+f"(d[3])
        : "r"(a[0]), "r"(a[1]), "r"(a[2]), "r"(a[3]), "r"(b[0]), "r"(b[1]));
}
// pair barrier: monotonic counter, 2 CTAs/pair, 128 CTAs all resident
__device__ __forceinline__ void psync(unsigned* ctr, unsigned &ep){
    __threadfence();
    __syncthreads();
    if (threadIdx.x == 0){
        ep += 2;
        atomicAdd(ctr, 1u);
        while (*(volatile unsigned*)ctr < ep) { }
    }
    __syncthreads();
    __threadfence();
}

// ---------------- setup: compact CSR of S (proven R1) ----------------
__global__ void build_csr(const float* __restrict__ S){
    __shared__ int cnt[NNODES+1];
    int t = threadIdx.x;
    for (int r = t; r < NNODES; r += blockDim.x){
        int c = 0;
        for (int j = 0; j < NNODES; j++) c += (S[r*NNODES + j] != 0.0f);
        cnt[r] = c;
    }
    __syncthreads();
    if (t == 0){
        int acc = 0;
        for (int r = 0; r < NNODES; r++){ int c = cnt[r]; cnt[r] = acc; acc += c; }
        cnt[NNODES] = acc;
    }
    __syncthreads();
    for (int r = t; r <= NNODES; r += blockDim.x) g_rowptr[r] = cnt[r];
    for (int r = t; r < NNODES; r += blockDim.x){
        int p = cnt[r];
        for (int j = 0; j < NNODES; j++){
            float v = S[r*NNODES + j];
            if (v != 0.0f){ g_cols[p] = j; g_vals[p] = v; p++; }
        }
    }
}

// ---------------- setup: folded + frag-packed weights (proven R9) ----------------
__device__ __forceinline__ float wmod(const float* W, int F, int FP, int ONUM, int k, int n){
    int sec = k / FP, col = k - sec*FP;
    if (sec > 2 || col >= F) return 0.f;
    if (sec == 0) return W[col*ONUM + n] - W[(2*F + col)*ONUM + n];
    if (sec == 1) return W[(F + col)*ONUM + n];
    return 2.f*W[(2*F + col)*ONUM + n];
}
__global__ void prep_w(const float* __restrict__ W, int F, int FP, int ONUM, int mat){
    int F3P = 3*FP, NKT = (F3P + 15)/16, NB8 = ONUM/8;
    int total = NB8*NKT*64;
    for (int idx = blockIdx.x*blockDim.x + threadIdx.x; idx < total; idx += gridDim.x*blockDim.x){
        int reg = idx & 1, lane = (idx >> 1) & 31;
        int t2 = idx >> 6; int kt = t2 % NKT, nb8 = t2 / NKT;
        int gg = lane >> 2, qq = lane & 3;
        int n  = nb8*8 + gg;
        int k0 = kt*16 + qq*2 + reg*8;
        float w0 = wmod(W, F, FP, ONUM, k0,     n);
        float w1 = wmod(W, F, FP, ONUM, k0 + 1, n);
        bf16 h0,l0,h1,l1; bfsplit(w0,h0,l0); bfsplit(w1,h1,l1);
        g_wph[mat][idx] = (unsigned)__bfloat16_as_ushort(h0) | ((unsigned)__bfloat16_as_ushort(h1) << 16);
        g_wpl[mat][idx] = (unsigned)__bfloat16_as_ushort(l0) | ((unsigned)__bfloat16_as_ushort(l1) << 16);
    }
}

// ---------------- sparse apply: rows [rbeg,rend), gathers all rows; 4-wide unroll, dual chains ----------------
template<int FP, bool WF32>
__device__ void sp_apply(float* xk, bf16* xh, bf16* xl, int src, int dst,
                         const ull* s_ent, const int* s_rp, int rbeg, int rend)
{
    const int G = FP >> 2;
    const int tasks = (rend - rbeg)*G;
    for (int t = threadIdx.x; t < tasks; t += NTH){
        int m = rbeg + t/G, f = (t - (t/G)*G)*4;
        const float* sp = xk + src + f;
        float ax0=0.f, ay0=0.f, az0=0.f, aw0=0.f;
        float ax1=0.f, ay1=0.f, az1=0.f, aw1=0.f;
        int j = s_rp[m], j1 = s_rp[m+1];
        for (; j + 3 < j1; j += 4){
            ull e0 = s_ent[j],   e1 = s_ent[j+1];
            ull e2 = s_ent[j+2], e3 = s_ent[j+3];
            float v0 = __uint_as_float((unsigned)(e0 >> 32));
            float v1 = __uint_as_float((unsigned)(e1 >> 32));
            float v2 = __uint_as_float((unsigned)(e2 >> 32));
            float v3 = __uint_as_float((unsigned)(e3 >> 32));
            float4 x0 = *(const float4*)(sp + (int)(unsigned)e0 * STRR);
            float4 x1 = *(const float4*)(sp + (int)(unsigned)e1 * STRR);
            float4 x2 = *(const float4*)(sp + (int)(unsigned)e2 * STRR);
            float4 x3 = *(const float4*)(sp + (int)(unsigned)e3 * STRR);
            ax0 += v0*x0.x + v2*x2.x;  ay0 += v0*x0.y + v2*x2.y;
            az0 += v0*x0.z + v2*x2.z;  aw0 += v0*x0.w + v2*x2.w;
            ax1 += v1*x1.x + v3*x3.x;  ay1 += v1*x1.y + v3*x3.y;
            az1 += v1*x1.z + v3*x3.z;  aw1 += v1*x1.w + v3*x3.w;
        }
        for (; j < j1; j++){
            ull e0 = s_ent[j];
            float v0 = __uint_as_float((unsigned)(e0 >> 32));
            float4 x0 = *(const float4*)(sp + (int)(unsigned)e0 * STRR);
            ax0 += v0*x0.x; ay0 += v0*x0.y; az0 += v0*x0.z; aw0 += v0*x0.w;
        }
        float ax = ax0 + ax1, ay = ay0 + ay1, az = az0 + az1, aw = aw0 + aw1;
        int o = m*STRR + dst + f;
        if (WF32) *(float4*)(xk + o) = make_float4(ax, ay, az, aw);
        bf16 hx,lx,hy,ly,hz,lz,hw,lw;
        bfsplit(ax,hx,lx); bfsplit(ay,hy,ly); bfsplit(az,hz,lz); bfsplit(aw,hw,lw);
        uint2 uh, ul2;
        uh.x  = (unsigned)__bfloat16_as_ushort(hx) | ((unsigned)__bfloat16_as_ushort(hy) << 16);
        uh.y  = (unsigned)__bfloat16_as_ushort(hz) | ((unsigned)__bfloat16_as_ushort(hw) << 16);
        ul2.x = (unsigned)__bfloat16_as_ushort(lx) | ((unsigned)__bfloat16_as_ushort(ly) << 16);
        ul2.y = (unsigned)__bfloat16_as_ushort(lz) | ((unsigned)__bfloat16_as_ushort(lw) << 16);
        *(uint2*)(xh + o) = uh;
        *(uint2*)(xl + o) = ul2;
    }
}

// ---------------- barrier-free mma GEMM chunk (direct-LDG A frags; reads OWN rows only) ----------------
template<int MW, int NW, int ONUM, int FP>
__device__ void gemm_chunk(int row0, int rowEnd,
    const bf16* __restrict__ xh, const bf16* __restrict__ xl,   // A-frag source
    float* xkB, bf16* xhB, bf16* xlB,                           // gate rh target (epi 0)
    const unsigned* __restrict__ wph, const unsigned* __restrict__ wpl,
    const float* __restrict__ bias, float* H, float* us, int epi, int FX,
    const float* __restrict__ pW, const float* __restrict__ pb,
    float* __restrict__ out_t, float* __restrict__ din, float* s_red)
{
    constexpr int NKT = (3*FP + 15)/16;
    constexpr int NA  = ONUM/(8*NW);
    constexpr int BM  = MW*32;
    const int tid = threadIdx.x, lane = tid & 31, wid = tid >> 5;
    const int mw = wid % MW, nw = wid / MW;
    const int g = lane >> 2, q = lane & 3;

    int aoff[4];
    #pragma unroll
    for (int i = 0; i < 4; i++){
        int r = row0 + mw*32 + i*8 + g;
        if (r > NNODES-1) r = NNODES-1;        // clamp stays within own-rank rows
        aoff[i] = r*STRR + q*2;
    }

    float acc[2][NA][4];
    #pragma unroll
    for (int i = 0; i < 2; i++)
        #pragma unroll
        for (int j = 0; j < NA; j++)
            #pragma unroll
            for (int k = 0; k < 4; k++) acc[i][j][k] = 0.f;

    unsigned aH[2][2][4], aL[2][2][4], bB[2][NA][4];

    auto ldA = [&](int kt, int st){
        int kk = kt*16;
        #pragma unroll
        for (int ma = 0; ma < 2; ma++){
            aH[st][ma][0] = *(const unsigned*)(xh + aoff[2*ma]   + kk);
            aH[st][ma][1] = *(const unsigned*)(xh + aoff[2*ma+1] + kk);
            aH[st][ma][2] = *(const unsigned*)(xh + aoff[2*ma]   + kk + 8);
            aH[st][ma][3] = *(const unsigned*)(xh + aoff[2*ma+1] + kk + 8);
            aL[st][ma][0] = *(const unsigned*)(xl + aoff[2*ma]   + kk);
            aL[st][ma][1] = *(const unsigned*)(xl + aoff[2*ma+1] + kk);
            aL[st][ma][2] = *(const unsigned*)(xl + aoff[2*ma]   + kk + 8);
            aL[st][ma][3] = *(const unsigned*)(xl + aoff[2*ma+1] + kk + 8);
        }
    };
    auto ldB = [&](int kt, int st){
        #pragma unroll
        for (int na = 0; na < NA; na++){
            int base = (((nw*NA + na)*NKT + kt)*32 + lane)*2;
            uint2 bh = *(const uint2*)(wph + base);
            uint2 bl = *(const uint2*)(wpl + base);
            bB[st][na][0] = bh.x; bB[st][na][1] = bh.y;
            bB[st][na][2] = bl.x; bB[st][na][3] = bl.y;
        }
    };

    ldA(0, 0); ldB(0, 0);
    for (int kt = 0; kt < NKT; kt++){
        int cur = kt & 1, nxt = cur ^ 1;
        if (kt + 1 < NKT){ ldA(kt+1, nxt); ldB(kt+1, nxt); }
        #pragma unroll
        for (int na = 0; na < NA; na++){
            unsigned bh[2] = {bB[cur][na][0], bB[cur][na][1]};
            unsigned bl[2] = {bB[cur][na][2], bB[cur][na][3]};
            #pragma unroll
            for (int ma = 0; ma < 2; ma++){
                mma16816(acc[ma][na], aH[cur][ma], bh);
                mma16816(acc[ma][na], aH[cur][ma], bl);
                mma16816(acc[ma][na], aL[cur][ma], bh);
            }
        }
    }

    float pvp[2][2] = {{0.f,0.f},{0.f,0.f}};
    #pragma unroll
    for (int ma = 0; ma < 2; ma++){
        #pragma unroll
        for (int na = 0; na < NA; na++){
            int n0 = nw*(8*NA) + na*8 + q*2;
            #pragma unroll
            for (int half = 0; half < 2; half++){
                int r = row0 + mw*32 + ma*16 + g + half*8;
                if (r >= rowEnd) continue;
                float v0 = acc[ma][na][half*2 + 0] + bias[n0];
                float v1 = acc[ma][na][half*2 + 1] + bias[n0 + 1];
                if (epi == 0){
                    float s0 = 1.f/(1.f + expf(-v0));
                    float s1 = 1.f/(1.f + expf(-v1));
                    if (n0 < UNITS){
                        float r0 = s0 * H[r*UNITS + n0];
                        float r1 = s1 * H[r*UNITS + n0 + 1];
                        int o = r*STRR + FX + n0;
                        xkB[o] = r0; xkB[o+1] = r1;
                        bf16 h, l;
                        bfsplit(r0, h, l); xhB[o] = h;   xlB[o] = l;
                        bfsplit(r1, h, l); xhB[o+1] = h; xlB[o+1] = l;
                    } else {
                        us[r*UNITS + (n0 - UNITS)]     = s0;
                        us[r*UNITS + (n0 - UNITS) + 1] = s1;
                    }
                } else {
                    float c0 = tanhf(v0), c1 = tanhf(v1);
                    float u0 = us[r*UNITS + n0],     u1 = us[r*UNITS + n0 + 1];
                    float h0v = H[r*UNITS + n0],     h1v = H[r*UNITS + n0 + 1];
                    float hn0 = u0*h0v + (1.f - u0)*c0;
                    float hn1 = u1*h1v + (1.f - u1)*c1;
                    H[r*UNITS + n0]     = hn0;
                    H[r*UNITS + n0 + 1] = hn1;
                    if (epi == 2) pvp[ma][half] += hn0*pW[n0] + hn1*pW[n0 + 1];
                }
            }
        }
    }
    if (epi == 2){
        #pragma unroll
        for (int ma = 0; ma < 2; ma++)
            #pragma unroll
            for (int half = 0; half < 2; half++){
                float v = pvp[ma][half];
                v += __shfl_down_sync(0xffffffffu, v, 2);
                v += __shfl_down_sync(0xffffffffu, v, 1);
                if (q == 0) s_red[(mw*32 + ma*16 + g + half*8)*NW + nw] = v;
            }
        __syncthreads();
        if (tid < BM){
            int r = row0 + tid;
            if (r < rowEnd){
                float v = pb[0];
                #pragma unroll
                for (int w2 = 0; w2 < NW; w2++) v += s_red[tid*NW + w2];
                din[r]  = v;
                out_t[r] = v;
            }
        }
        __syncthreads();
    }
}

// ---------------- one GRU cell: 2 pair-syncs (x1/rh1 duplicate-computed for ALL rows) ----------------
template<int FX, int F, int FP>
__device__ void cell_run(int b, int rbeg, int rend,
                         const float* __restrict__ xptr, float* H,
                         int matg, int matc,
                         const float* gb, const float* cb, int epi_cand,
                         const float* pW, const float* pb, float* out_t,
                         unsigned* ctr, unsigned &ep,
                         const ull* s_ent, const int* s_rp, float* s_red)
{
    float* xkA = g_xkA + b*XKSTR;  bf16* xhA = g_xhA + b*XKSTR;  bf16* xlA = g_xlA + b*XKSTR;
    float* xkB = g_xkB + b*XKSTR;  bf16* xhB = g_xhB + b*XKSTR;  bf16* xlB = g_xlB + b*XKSTR;
    float* us  = g_u   + b*NNODES*UNITS;
    float* din = g_din + b*NNODES;

    __syncthreads();   // prev-cell H/din (own-CTA cross-warp)
    // concat own rows: A.x0 = [x, h] + pads ; B.x0 x-cols + pads
    for (int idx = threadIdx.x; idx < (rend - rbeg)*FP; idx += NTH){
        int m = rbeg + idx/FP, f = idx - (idx/FP)*FP;
        int o = m*STRR + f;
        float v;
        bf16 h, l;
        if (f >= F){
            xkA[o] = 0.f; xhA[o] = __float2bfloat16(0.f); xlA[o] = __float2bfloat16(0.f);
            xkB[o] = 0.f; xhB[o] = __float2bfloat16(0.f); xlB[o] = __float2bfloat16(0.f);
            continue;
        }
        if (f < FX){
            v = (FX == 2) ? xptr[m*DIN + f] : ((FX == 1) ? xptr[m] : xptr[m*UNITS + f]);
            bfsplit(v, h, l);
            xkA[o] = v; xhA[o] = h; xlA[o] = l;
            xkB[o] = v; xhB[o] = h; xlB[o] = l;
        } else {
            v = H[m*UNITS + (f - FX)];
            bfsplit(v, h, l);
            xkA[o] = v; xhA[o] = h; xlA[o] = l;
        }
    }
    psync(ctr, ep);                                                  // (a) x0 all rows ready
    // x1 for ALL rows (duplicate compute, bitwise identical across pair)
    sp_apply<FP,true >(xkA, xhA, xlA, 0,  FP,   s_ent, s_rp, 0, NNODES);
    __syncthreads();
    // x2 own rows (x1 values self-computed -> no pair sync needed)
    sp_apply<FP,false>(xkA, xhA, xlA, FP, 2*FP, s_ent, s_rp, rbeg, rend);
    __syncthreads();
    gemm_chunk<4,4,128,FP>(rbeg,       rend, xhA, xlA, xkB, xhB, xlB,
        g_wph[matg], g_wpl[matg], gb, H, us, 0, FX, nullptr, nullptr, nullptr, din, s_red);
    gemm_chunk<2,8,128,FP>(rbeg + 128, rend, xhA, xlA, xkB, xhB, xlB,
        g_wph[matg], g_wpl[matg], gb, H, us, 0, FX, nullptr, nullptr, nullptr, din, s_red);
    psync(ctr, ep);                                                  // (c) B.x0 (rh) all rows
    sp_apply<FP,true >(xkB, xhB, xlB, 0,  FP,   s_ent, s_rp, 0, NNODES);   // rh1 ALL rows
    __syncthreads();
    sp_apply<FP,false>(xkB, xhB, xlB, FP, 2*FP, s_ent, s_rp, rbeg, rend);  // rh2 own rows
    __syncthreads();
    gemm_chunk<4,4,64,FP>(rbeg,       rend, xhB, xlB, xkB, xhB, xlB,
        g_wph[matc], g_wpl[matc], cb, H, us, epi_cand, FX, pW, pb, out_t, din, s_red);
    gemm_chunk<2,8,64,FP>(rbeg + 128, rend, xhB, xlB, xkB, xhB, xlB,
        g_wph[matc], g_wpl[matc], cb, H, us, epi_cand, FX, pW, pb, out_t, din, s_red);
    // no cell-end psync: uniform stride makes rows address-disjoint; (a) orders transitively
}

// ---------------- the whole network: 2 CTAs per batch (node split at 192) ----------------
__global__ void __launch_bounds__(NTH, 1)
dcrnn_pair(const float* __restrict__ inputs,
           const float* e0gb, const float* e0cb,
           const float* e1gb, const float* e1cb,
           const float* d0gb, const float* d0cb,
           const float* d1gb, const float* d1cb,
           const float* pW, const float* pb, float* __restrict__ out)
{
    __shared__ ull s_ent[MAXE];
    __shared__ int s_rp[NNODES+1];
    __shared__ float s_red[128*8];

    const int b = blockIdx.x >> 1, rank = blockIdx.x & 1;
    const int rbeg = rank ? SPLIT : 0;
    const int rend = rank ? NNODES : SPLIT;
    const int tid = threadIdx.x;
    unsigned* ctr = &g_pbar[b];
    unsigned ep = 0;

    // CSR -> smem
    int nnz = g_rowptr[NNODES]; if (nnz > MAXE) nnz = MAXE;
    for (int j = tid; j < nnz; j += NTH)
        s_ent[j] = ((ull)__float_as_uint(g_vals[j]) << 32) | (unsigned)g_cols[j];
    for (int r = tid; r <= NNODES; r += NTH)
        s_rp[r] = (g_rowptr[r] > MAXE) ? MAXE : g_rowptr[r];
    // zero own state
    float* h0  = g_h0 + b*NNODES*UNITS;
    float* h1  = g_h1 + b*NNODES*UNITS;
    float* din = g_din + b*NNODES;
    for (int i = tid; i < (rend - rbeg)*UNITS; i += NTH)
        { h0[rbeg*UNITS + i] = 0.f; h1[rbeg*UNITS + i] = 0.f; }
    for (int i = tid; i < rend - rbeg; i += NTH) din[rbeg + i] = 0.f;

    // ---- encoder ----
    for (int t = 0; t < TSTEPS; t++){
        const float* xin = inputs + ((size_t)t*BATCH + b)*NNODES*DIN;
        cell_run<2,66,68>(b, rbeg, rend, xin, h0, 0, 4, e0gb, e0cb, 1,
                          nullptr, nullptr, nullptr, ctr, ep, s_ent, s_rp, s_red);
        cell_run<64,128,128>(b, rbeg, rend, h0, h1, 1, 5, e1gb, e1cb, 1,
                          nullptr, nullptr, nullptr, ctr, ep, s_ent, s_rp, s_red);
    }
    // ---- decoder ----
    for (int t = 0; t < HORIZON; t++){
        cell_run<1,65,68>(b, rbeg, rend, din, h0, 2, 6, d0gb, d0cb, 1,
                          nullptr, nullptr, nullptr, ctr, ep, s_ent, s_rp, s_red);
        cell_run<64,128,128>(b, rbeg, rend, h0, h1, 3, 7, d1gb, d1cb, 2,
                          pW, pb, out + ((size_t)t*BATCH + b)*NNODES,
                          ctr, ep, s_ent, s_rp, s_red);
    }
}

extern "C" void kernel_launch(void* const* d_in, const int* in_sizes, int n_in,
                              void* d_out, int out_size)
{
    const float* inputs  = (const float*)d_in[0];
    const float* support = (const float*)d_in[1];
    const float* e0gW = (const float*)d_in[2];  const float* e0gb = (const float*)d_in[3];
    const float* e0cW = (const float*)d_in[4];  const float* e0cb = (const float*)d_in[5];
    const float* e1gW = (const float*)d_in[6];  const float* e1gb = (const float*)d_in[7];
    const float* e1cW = (const float*)d_in[8];  const float* e1cb = (const float*)d_in[9];
    const float* d0gW = (const float*)d_in[10]; const float* d0gb = (const float*)d_in[11];
    const float* d0cW = (const float*)d_in[12]; const float* d0cb = (const float*)d_in[13];
    const float* d1gW = (const float*)d_in[14]; const float* d1gb = (const float*)d_in[15];
    const float* d1cW = (const float*)d_in[16]; const float* d1cb = (const float*)d_in[17];
    const float* pW   = (const float*)d_in[18]; const float* pb   = (const float*)d_in[19];
    float* out = (float*)d_out;

    init_pbar<<<1, BATCH>>>();
    build_csr<<<1, 352>>>(support);
    // fold + frag-pack weights: gate mats 0..3, cand mats 4..7
    prep_w<<<48, 256>>>(e0gW, 66, 68, 128, 0);
    prep_w<<<48, 256>>>(e1gW, 128, 128, 128, 1);
    prep_w<<<48, 256>>>(d0gW, 65, 68, 128, 2);
    prep_w<<<48, 256>>>(d1gW, 128, 128, 128, 3);
    prep_w<<<48, 256>>>(e0cW, 66, 68, 64, 4);
    prep_w<<<48, 256>>>(e1cW, 128, 128, 64, 5);
    prep_w<<<48, 256>>>(d0cW, 65, 68, 64, 6);
    prep_w<<<48, 256>>>(d1cW, 128, 128, 64, 7);

    dcrnn_pair<<<2*BATCH, NTH>>>(inputs,
        e0gb, e0cb, e1gb, e1cb, d0gb, d0cb, d1gb, d1cb,
        pW, pb, out);
}

// round 14
// speedup vs baseline: 1.0667x; 1.0667x over previous
#include <cuda_runtime.h>
#include <cuda_bf16.h>
#include <math.h>

// ---------------- problem constants ----------------
#define NNODES 325
#define BATCH  64
#define TSTEPS 12
#define HORIZON 12
#define UNITS  64
#define DIN    2
#define XKSTR  (NNODES*384)
#define NTH    512
#define SPLIT  192               // rank0 rows [0,192) (=128+64 exact), rank1 [192,325)
#define MAXE   2600
#define WPMAX  32768
#define MAXNNZ 110000

typedef unsigned long long ull;
typedef __nv_bfloat16 bf16;

// ---------------- device scratch (A basis = [x,h]; B basis = [x,rh]) ----------------
__device__ __align__(16) float g_xkA[BATCH*XKSTR];
__device__ __align__(16) bf16  g_xhA[BATCH*XKSTR];
__device__ __align__(16) bf16  g_xlA[BATCH*XKSTR];
__device__ __align__(16) float g_xkB[BATCH*XKSTR];
__device__ __align__(16) bf16  g_xhB[BATCH*XKSTR];
__device__ __align__(16) bf16  g_xlB[BATCH*XKSTR];
__device__ float g_h0[BATCH*NNODES*UNITS];
__device__ float g_h1[BATCH*NNODES*UNITS];
__device__ float g_u [BATCH*NNODES*UNITS];
__device__ float g_din[BATCH*NNODES];
__device__ int   g_rowptr[NNODES+1];
__device__ int   g_cols[MAXNNZ];
__device__ float g_vals[MAXNNZ];
__device__ unsigned g_wph[8][WPMAX];
__device__ unsigned g_wpl[8][WPMAX];
__device__ unsigned g_pbar[BATCH];

__global__ void init_pbar(){ if (threadIdx.x < BATCH) g_pbar[threadIdx.x] = 0u; }

// ---------------- helpers ----------------
__device__ __forceinline__ void bfsplit(float a, bf16 &h, bf16 &l){
    h = __float2bfloat16(a);
    l = __float2bfloat16(a - __bfloat162float(h));
}
__device__ __forceinline__ void mma16816(float* d, const unsigned* a, const unsigned* b){
    asm volatile("mma.sync.aligned.m16n8k16.row.col.f32.bf16.bf16.f32 "
        "{%0,%1,%2,%3}, {%4,%5,%6,%7}, {%8,%9}, {%0,%1,%2,%3};"
        : "+f"(d[0]), "+f"(d[1]), "+f"(d[2]), "+f"(d[3])
        : "r"(a[0]), "r"(a[1]), "r"(a[2]), "r"(a[3]), "r"(b[0]), "r"(b[1]));
}
// pair barrier, FULL: release fence + acquire fence (L1 flush both sides)
__device__ __forceinline__ void psync(unsigned* ctr, unsigned &ep){
    __threadfence();
    __syncthreads();
    if (threadIdx.x == 0){
        ep += 2;
        atomicAdd(ctr, 1u);
        while (*(volatile unsigned*)ctr < ep) { }
    }
    __syncthreads();
    __threadfence();
}
// pair barrier, RELEASE-ONLY: drains stores before arrival; no acquire flush.
// Safe when no post-barrier read consumes peer-fresh data before the next full psync.
__device__ __forceinline__ void psync_rel(unsigned* ctr, unsigned &ep){
    __threadfence();
    __syncthreads();
    if (threadIdx.x == 0){
        ep += 2;
        atomicAdd(ctr, 1u);
        while (*(volatile unsigned*)ctr < ep) { }
    }
    __syncthreads();
}

// ---------------- setup: compact CSR of S (proven R1) ----------------
__global__ void build_csr(const float* __restrict__ S){
    __shared__ int cnt[NNODES+1];
    int t = threadIdx.x;
    for (int r = t; r < NNODES; r += blockDim.x){
        int c = 0;
        for (int j = 0; j < NNODES; j++) c += (S[r*NNODES + j] != 0.0f);
        cnt[r] = c;
    }
    __syncthreads();
    if (t == 0){
        int acc = 0;
        for (int r = 0; r < NNODES; r++){ int c = cnt[r]; cnt[r] = acc; acc += c; }
        cnt[NNODES] = acc;
    }
    __syncthreads();
    for (int r = t; r <= NNODES; r += blockDim.x) g_rowptr[r] = cnt[r];
    for (int r = t; r < NNODES; r += blockDim.x){
        int p = cnt[r];
        for (int j = 0; j < NNODES; j++){
            float v = S[r*NNODES + j];
            if (v != 0.0f){ g_cols[p] = j; g_vals[p] = v; p++; }
        }
    }
}

// ---------------- setup: folded + frag-packed weights (proven R9) ----------------
__device__ __forceinline__ float wmod(const float* W, int F, int FP, int ONUM, int k, int n){
    int sec = k / FP, col = k - sec*FP;
    if (sec > 2 || col >= F) return 0.f;
    if (sec == 0) return W[col*ONUM + n] - W[(2*F + col)*ONUM + n];
    if (sec == 1) return W[(F + col)*ONUM + n];
    return 2.f*W[(2*F + col)*ONUM + n];
}
__global__ void prep_w(const float* __restrict__ W, int F, int FP, int ONUM, int mat){
    int F3P = 3*FP, NKT = (F3P + 15)/16, NB8 = ONUM/8;
    int total = NB8*NKT*64;
    for (int idx = blockIdx.x*blockDim.x + threadIdx.x; idx < total; idx += gridDim.x*blockDim.x){
        int reg = idx & 1, lane = (idx >> 1) & 31;
        int t2 = idx >> 6; int kt = t2 % NKT, nb8 = t2 / NKT;
        int gg = lane >> 2, qq = lane & 3;
        int n  = nb8*8 + gg;
        int k0 = kt*16 + qq*2 + reg*8;
        float w0 = wmod(W, F, FP, ONUM, k0,     n);
        float w1 = wmod(W, F, FP, ONUM, k0 + 1, n);
        bf16 h0,l0,h1,l1; bfsplit(w0,h0,l0); bfsplit(w1,h1,l1);
        g_wph[mat][idx] = (unsigned)__bfloat16_as_ushort(h0) | ((unsigned)__bfloat16_as_ushort(h1) << 16);
        g_wpl[mat][idx] = (unsigned)__bfloat16_as_ushort(l0) | ((unsigned)__bfloat16_as_ushort(l1) << 16);
    }
}

// ---------------- sparse apply: rows [rbeg,rend), gathers all rows; 4-wide unroll ----------------
template<int FP, int STRR, bool WF32>
__device__ void sp_apply(float* xk, bf16* xh, bf16* xl, int src, int dst,
                         const ull* s_ent, const int* s_rp, int rbeg, int rend)
{
    const int G = FP >> 2;
    const int tasks = (rend - rbeg)*G;
    for (int t = threadIdx.x; t < tasks; t += NTH){
        int m = rbeg + t/G, f = (t - (t/G)*G)*4;
        const float* sp = xk + src + f;
        float ax0=0.f, ay0=0.f, az0=0.f, aw0=0.f;
        float ax1=0.f, ay1=0.f, az1=0.f, aw1=0.f;
        int j = s_rp[m], j1 = s_rp[m+1];
        for (; j + 3 < j1; j += 4){
            ull e0 = s_ent[j],   e1 = s_ent[j+1];
            ull e2 = s_ent[j+2], e3 = s_ent[j+3];
            float v0 = __uint_as_float((unsigned)(e0 >> 32));
            float v1 = __uint_as_float((unsigned)(e1 >> 32));
            float v2 = __uint_as_float((unsigned)(e2 >> 32));
            float v3 = __uint_as_float((unsigned)(e3 >> 32));
            float4 x0 = *(const float4*)(sp + (int)(unsigned)e0 * STRR);
            float4 x1 = *(const float4*)(sp + (int)(unsigned)e1 * STRR);
            float4 x2 = *(const float4*)(sp + (int)(unsigned)e2 * STRR);
            float4 x3 = *(const float4*)(sp + (int)(unsigned)e3 * STRR);
            ax0 += v0*x0.x + v2*x2.x;  ay0 += v0*x0.y + v2*x2.y;
            az0 += v0*x0.z + v2*x2.z;  aw0 += v0*x0.w + v2*x2.w;
            ax1 += v1*x1.x + v3*x3.x;  ay1 += v1*x1.y + v3*x3.y;
            az1 += v1*x1.z + v3*x3.z;  aw1 += v1*x1.w + v3*x3.w;
        }
        for (; j < j1; j++){
            ull e0 = s_ent[j];
            float v0 = __uint_as_float((unsigned)(e0 >> 32));
            float4 x0 = *(const float4*)(sp + (int)(unsigned)e0 * STRR);
            ax0 += v0*x0.x; ay0 += v0*x0.y; az0 += v0*x0.z; aw0 += v0*x0.w;
        }
        float ax = ax0 + ax1, ay = ay0 + ay1, az = az0 + az1, aw = aw0 + aw1;
        int o = m*STRR + dst + f;
        if (WF32) *(float4*)(xk + o) = make_float4(ax, ay, az, aw);
        bf16 hx,lx,hy,ly,hz,lz,hw,lw;
        bfsplit(ax,hx,lx); bfsplit(ay,hy,ly); bfsplit(az,hz,lz); bfsplit(aw,hw,lw);
        uint2 uh, ul2;
        uh.x  = (unsigned)__bfloat16_as_ushort(hx) | ((unsigned)__bfloat16_as_ushort(hy) << 16);
        uh.y  = (unsigned)__bfloat16_as_ushort(hz) | ((unsigned)__bfloat16_as_ushort(hw) << 16);
        ul2.x = (unsigned)__bfloat16_as_ushort(lx) | ((unsigned)__bfloat16_as_ushort(ly) << 16);
        ul2.y = (unsigned)__bfloat16_as_ushort(lz) | ((unsigned)__bfloat16_as_ushort(lw) << 16);
        *(uint2*)(xh + o) = uh;
        *(uint2*)(xl + o) = ul2;
    }
}

// ---------------- barrier-free mma GEMM chunk (direct-LDG A frags; reads OWN rows only) ----------------
// epi 0 (gate): s=sigmoid; n<64 -> rh into B buffers x0[FX+n]; n>=64 -> g_u
// epi 1 (cand): c=tanh; H = u*H + (1-u)*c
// epi 2: epi1 + fused projection -> out_t, din
template<int MW, int NW, int ONUM, int FP, int STRR>
__device__ void gemm_chunk(int row0, int rowEnd,
    const bf16* __restrict__ xh, const bf16* __restrict__ xl,   // A-frag source
    float* xkB, bf16* xhB, bf16* xlB,                           // gate rh target (epi 0)
    const unsigned* __restrict__ wph, const unsigned* __restrict__ wpl,
    const float* __restrict__ bias, float* H, float* us, int epi, int FX,
    const float* __restrict__ pW, const float* __restrict__ pb,
    float* __restrict__ out_t, float* __restrict__ din, float* s_red)
{
    constexpr int NKT = (3*FP + 15)/16;
    constexpr int NA  = ONUM/(8*NW);
    constexpr int BM  = MW*32;
    const int tid = threadIdx.x, lane = tid & 31, wid = tid >> 5;
    const int mw = wid % MW, nw = wid / MW;
    const int g = lane >> 2, q = lane & 3;

    int aoff[4];
    #pragma unroll
    for (int i = 0; i < 4; i++){
        int r = row0 + mw*32 + i*8 + g;
        if (r > NNODES-1) r = NNODES-1;        // clamp stays within own-rank rows
        aoff[i] = r*STRR + q*2;
    }

    float acc[2][NA][4];
    #pragma unroll
    for (int i = 0; i < 2; i++)
        #pragma unroll
        for (int j = 0; j < NA; j++)
            #pragma unroll
            for (int k = 0; k < 4; k++) acc[i][j][k] = 0.f;

    unsigned aH[2][2][4], aL[2][2][4], bB[2][NA][4];

    auto ldA = [&](int kt, int st){
        int kk = kt*16;
        #pragma unroll
        for (int ma = 0; ma < 2; ma++){
            aH[st][ma][0] = *(const unsigned*)(xh + aoff[2*ma]   + kk);
            aH[st][ma][1] = *(const unsigned*)(xh + aoff[2*ma+1] + kk);
            aH[st][ma][2] = *(const unsigned*)(xh + aoff[2*ma]   + kk + 8);
            aH[st][ma][3] = *(const unsigned*)(xh + aoff[2*ma+1] + kk + 8);
            aL[st][ma][0] = *(const unsigned*)(xl + aoff[2*ma]   + kk);
            aL[st][ma][1] = *(const unsigned*)(xl + aoff[2*ma+1] + kk);
            aL[st][ma][2] = *(const unsigned*)(xl + aoff[2*ma]   + kk + 8);
            aL[st][ma][3] = *(const unsigned*)(xl + aoff[2*ma+1] + kk + 8);
        }
    };
    auto ldB = [&](int kt, int st){
        #pragma unroll
        for (int na = 0; na < NA; na++){
            int base = (((nw*NA + na)*NKT + kt)*32 + lane)*2;
            uint2 bh = *(const uint2*)(wph + base);
            uint2 bl = *(const uint2*)(wpl + base);
            bB[st][na][0] = bh.x; bB[st][na][1] = bh.y;
            bB[st][na][2] = bl.x; bB[st][na][3] = bl.y;
        }
    };

    ldA(0, 0); ldB(0, 0);
    for (int kt = 0; kt < NKT; kt++){
        int cur = kt & 1, nxt = cur ^ 1;
        if (kt + 1 < NKT){ ldA(kt+1, nxt); ldB(kt+1, nxt); }
        #pragma unroll
        for (int na = 0; na < NA; na++){
            unsigned bh[2] = {bB[cur][na][0], bB[cur][na][1]};
            unsigned bl[2] = {bB[cur][na][2], bB[cur][na][3]};
            #pragma unroll
            for (int ma = 0; ma < 2; ma++){
                mma16816(acc[ma][na], aH[cur][ma], bh);
                mma16816(acc[ma][na], aH[cur][ma], bl);
                mma16816(acc[ma][na], aL[cur][ma], bh);
            }
        }
    }

    float pvp[2][2] = {{0.f,0.f},{0.f,0.f}};
    #pragma unroll
    for (int ma = 0; ma < 2; ma++){
        #pragma unroll
        for (int na = 0; na < NA; na++){
            int n0 = nw*(8*NA) + na*8 + q*2;
            #pragma unroll
            for (int half = 0; half < 2; half++){
                int r = row0 + mw*32 + ma*16 + g + half*8;
                if (r >= rowEnd) continue;
                float v0 = acc[ma][na][half*2 + 0] + bias[n0];
                float v1 = acc[ma][na][half*2 + 1] + bias[n0 + 1];
                if (epi == 0){
                    float s0 = 1.f/(1.f + expf(-v0));
                    float s1 = 1.f/(1.f + expf(-v1));
                    if (n0 < UNITS){
                        float r0 = s0 * H[r*UNITS + n0];
                        float r1 = s1 * H[r*UNITS + n0 + 1];
                        int o = r*STRR + FX + n0;
                        xkB[o] = r0; xkB[o+1] = r1;
                        bf16 h, l;
                        bfsplit(r0, h, l); xhB[o] = h;   xlB[o] = l;
                        bfsplit(r1, h, l); xhB[o+1] = h; xlB[o+1] = l;
                    } else {
                        us[r*UNITS + (n0 - UNITS)]     = s0;
                        us[r*UNITS + (n0 - UNITS) + 1] = s1;
                    }
                } else {
                    float c0 = tanhf(v0), c1 = tanhf(v1);
                    float u0 = us[r*UNITS + n0],     u1 = us[r*UNITS + n0 + 1];
                    float h0v = H[r*UNITS + n0],     h1v = H[r*UNITS + n0 + 1];
                    float hn0 = u0*h0v + (1.f - u0)*c0;
                    float hn1 = u1*h1v + (1.f - u1)*c1;
                    H[r*UNITS + n0]     = hn0;
                    H[r*UNITS + n0 + 1] = hn1;
                    if (epi == 2) pvp[ma][half] += hn0*pW[n0] + hn1*pW[n0 + 1];
                }
            }
        }
    }
    if (epi == 2){
        #pragma unroll
        for (int ma = 0; ma < 2; ma++)
            #pragma unroll
            for (int half = 0; half < 2; half++){
                float v = pvp[ma][half];
                v += __shfl_down_sync(0xffffffffu, v, 2);
                v += __shfl_down_sync(0xffffffffu, v, 1);
                if (q == 0) s_red[(mw*32 + ma*16 + g + half*8)*NW + nw] = v;
            }
        __syncthreads();
        if (tid < BM){
            int r = row0 + tid;
            if (r < rowEnd){
                float v = pb[0];
                #pragma unroll
                for (int w2 = 0; w2 < NW; w2++) v += s_red[tid*NW + w2];
                din[r]  = v;
                out_t[r] = v;
            }
        }
        __syncthreads();
    }
}

// ---------------- one GRU cell: 3 pair-syncs; x1/rh1 duplicate-computed for ALL rows ----------------
template<int FX, int F, int FP, int STRR>
__device__ void cell_run(int b, int rbeg, int rend,
                         const float* __restrict__ xptr, float* H,
                         int matg, int matc,
                         const float* gb, const float* cb, int epi_cand,
                         const float* pW, const float* pb, float* out_t,
                         unsigned* ctr, unsigned &ep,
                         const ull* s_ent, const int* s_rp, float* s_red)
{
    float* xkA = g_xkA + b*XKSTR;  bf16* xhA = g_xhA + b*XKSTR;  bf16* xlA = g_xlA + b*XKSTR;
    float* xkB = g_xkB + b*XKSTR;  bf16* xhB = g_xhB + b*XKSTR;  bf16* xlB = g_xlB + b*XKSTR;
    float* us  = g_u   + b*NNODES*UNITS;
    float* din = g_din + b*NNODES;

    __syncthreads();   // prev-cell H/din (own-CTA cross-warp)
    // concat own rows: A.x0 = [x, h] + pads ; B.x0 x-cols + pads
    for (int idx = threadIdx.x; idx < (rend - rbeg)*FP; idx += NTH){
        int m = rbeg + idx/FP, f = idx - (idx/FP)*FP;
        int o = m*STRR + f;
        float v;
        bf16 h, l;
        if (f >= F){
            xkA[o] = 0.f; xhA[o] = __float2bfloat16(0.f); xlA[o] = __float2bfloat16(0.f);
            xkB[o] = 0.f; xhB[o] = __float2bfloat16(0.f); xlB[o] = __float2bfloat16(0.f);
            continue;
        }
        if (f < FX){
            v = (FX == 2) ? xptr[m*DIN + f] : ((FX == 1) ? xptr[m] : xptr[m*UNITS + f]);
            bfsplit(v, h, l);
            xkA[o] = v; xhA[o] = h; xlA[o] = l;
            xkB[o] = v; xhB[o] = h; xlB[o] = l;
        } else {
            v = H[m*UNITS + (f - FX)];
            bfsplit(v, h, l);
            xkA[o] = v; xhA[o] = h; xlA[o] = l;
        }
    }
    psync(ctr, ep);                                                    // (a) x0 all rows ready
    // x1 for ALL rows — duplicate compute, bitwise identical across the pair
    sp_apply<FP,STRR,true >(xkA, xhA, xlA, 0,  FP,   s_ent, s_rp, 0, NNODES);
    __syncthreads();
    // x2 own rows (x1 self-computed -> CTA-local sync suffices)
    sp_apply<FP,STRR,false>(xkA, xhA, xlA, FP, 2*FP, s_ent, s_rp, rbeg, rend);
    __syncthreads();
    gemm_chunk<4,4,128,FP,STRR>(rbeg,       rend, xhA, xlA, xkB, xhB, xlB,
        g_wph[matg], g_wpl[matg], gb, H, us, 0, FX, nullptr, nullptr, nullptr, din, s_red);
    gemm_chunk<2,8,128,FP,STRR>(rbeg + 128, rend, xhA, xlA, xkB, xhB, xlB,
        g_wph[matg], g_wpl[matg], gb, H, us, 0, FX, nullptr, nullptr, nullptr, din, s_red);
    psync(ctr, ep);                                                    // (c) B.x0 (rh) all rows
    // rh1 for ALL rows — duplicate compute
    sp_apply<FP,STRR,true >(xkB, xhB, xlB, 0,  FP,   s_ent, s_rp, 0, NNODES);
    __syncthreads();
    sp_apply<FP,STRR,false>(xkB, xhB, xlB, FP, 2*FP, s_ent, s_rp, rbeg, rend);
    __syncthreads();
    gemm_chunk<4,4,64,FP,STRR>(rbeg,       rend, xhB, xlB, xkB, xhB, xlB,
        g_wph[matc], g_wpl[matc], cb, H, us, epi_cand, FX, pW, pb, out_t, din, s_red);
    gemm_chunk<2,8,64,FP,STRR>(rbeg + 128, rend, xhB, xlB, xkB, xhB, xlB,
        g_wph[matc], g_wpl[matc], cb, H, us, epi_cand, FX, pW, pb, out_t, din, s_red);
    psync_rel(ctr, ep);    // (e) cell end: anti-dependence across stride flip only.
                           //     Release fence drains peer-visible stores; no fresh
                           //     cross-CTA reads before next (a) -> no acquire flush.
}

// ---------------- the whole network: 2 CTAs per batch (node split at 192) ----------------
__global__ void __launch_bounds__(NTH, 1)
dcrnn_pair(const float* __restrict__ inputs,
           const float* e0gb, const float* e0cb,
           const float* e1gb, const float* e1cb,
           const float* d0gb, const float* d0cb,
           const float* d1gb, const float* d1cb,
           const float* pW, const float* pb, float* __restrict__ out)
{
    __shared__ ull s_ent[MAXE];
    __shared__ int s_rp[NNODES+1];
    __shared__ float s_red[128*8];

    const int b = blockIdx.x >> 1, rank = blockIdx.x & 1;
    const int rbeg = rank ? SPLIT : 0;
    const int rend = rank ? NNODES : SPLIT;
    const int tid = threadIdx.x;
    unsigned* ctr = &g_pbar[b];
    unsigned ep = 0;

    // CSR -> smem
    int nnz = g_rowptr[NNODES]; if (nnz > MAXE) nnz = MAXE;
    for (int j = tid; j < nnz; j += NTH)
        s_ent[j] = ((ull)__float_as_uint(g_vals[j]) << 32) | (unsigned)g_cols[j];
    for (int r = tid; r <= NNODES; r += NTH)
        s_rp[r] = (g_rowptr[r] > MAXE) ? MAXE : g_rowptr[r];
    // zero own state
    float* h0  = g_h0 + b*NNODES*UNITS;
    float* h1  = g_h1 + b*NNODES*UNITS;
    float* din = g_din + b*NNODES;
    for (int i = tid; i < (rend - rbeg)*UNITS; i += NTH)
        { h0[rbeg*UNITS + i] = 0.f; h1[rbeg*UNITS + i] = 0.f; }
    for (int i = tid; i < rend - rbeg; i += NTH) din[rbeg + i] = 0.f;

    // ---- encoder ----
    for (int t = 0; t < TSTEPS; t++){
        const float* xin = inputs + ((size_t)t*BATCH + b)*NNODES*DIN;
        cell_run<2,66,68,208>(b, rbeg, rend, xin, h0, 0, 4, e0gb, e0cb, 1,
                              nullptr, nullptr, nullptr, ctr, ep, s_ent, s_rp, s_red);
        cell_run<64,128,128,384>(b, rbeg, rend, h0, h1, 1, 5, e1gb, e1cb, 1,
                              nullptr, nullptr, nullptr, ctr, ep, s_ent, s_rp, s_red);
    }
    // ---- decoder ----
    for (int t = 0; t < HORIZON; t++){
        cell_run<1,65,68,208>(b, rbeg, rend, din, h0, 2, 6, d0gb, d0cb, 1,
                              nullptr, nullptr, nullptr, ctr, ep, s_ent, s_rp, s_red);
        cell_run<64,128,128,384>(b, rbeg, rend, h0, h1, 3, 7, d1gb, d1cb, 2,
                              pW, pb, out + ((size_t)t*BATCH + b)*NNODES,
                              ctr, ep, s_ent, s_rp, s_red);
    }
}

extern "C" void kernel_launch(void* const* d_in, const int* in_sizes, int n_in,
                              void* d_out, int out_size)
{
    const float* inputs  = (const float*)d_in[0];
    const float* support = (const float*)d_in[1];
    const float* e0gW = (const float*)d_in[2];  const float* e0gb = (const float*)d_in[3];
    const float* e0cW = (const float*)d_in[4];  const float* e0cb = (const float*)d_in[5];
    const float* e1gW = (const float*)d_in[6];  const float* e1gb = (const float*)d_in[7];
    const float* e1cW = (const float*)d_in[8];  const float* e1cb = (const float*)d_in[9];
    const float* d0gW = (const float*)d_in[10]; const float* d0gb = (const float*)d_in[11];
    const float* d0cW = (const float*)d_in[12]; const float* d0cb = (const float*)d_in[13];
    const float* d1gW = (const float*)d_in[14]; const float* d1gb = (const float*)d_in[15];
    const float* d1cW = (const float*)d_in[16]; const float* d1cb = (const float*)d_in[17];
    const float* pW   = (const float*)d_in[18]; const float* pb   = (const float*)d_in[19];
    float* out = (float*)d_out;

    init_pbar<<<1, BATCH>>>();
    build_csr<<<1, 352>>>(support);
    // fold + frag-pack weights: gate mats 0..3, cand mats 4..7
    prep_w<<<48, 256>>>(e0gW, 66, 68, 128, 0);
    prep_w<<<48, 256>>>(e1gW, 128, 128, 128, 1);
    prep_w<<<48, 256>>>(d0gW, 65, 68, 128, 2);
    prep_w<<<48, 256>>>(d1gW, 128, 128, 128, 3);
    prep_w<<<48, 256>>>(e0cW, 66, 68, 64, 4);
    prep_w<<<48, 256>>>(e1cW, 128, 128, 64, 5);
    prep_w<<<48, 256>>>(d0cW, 65, 68, 64, 6);
    prep_w<<<48, 256>>>(d1cW, 128, 128, 64, 7);

    dcrnn_pair<<<2*BATCH, NTH>>>(inputs,
        e0gb, e0cb, e1gb, e1cb, d0gb, d0cb, d1gb, d1cb,
        pW, pb, out);
}

// round 15
// speedup vs baseline: 1.0952x; 1.0267x over previous
#include <cuda_runtime.h>
#include <cuda_bf16.h>
#include <math.h>

// ---------------- problem constants ----------------
#define NNODES 325
#define BATCH  64
#define TSTEPS 12
#define HORIZON 12
#define UNITS  64
#define DIN    2
#define XKSTR  (NNODES*384)
#define NTH    512
#define SPLIT  192               // rank0 rows [0,192) (=128+64 exact), rank1 [192,325)
#define MAXE   2600
#define WPMAX  32768
#define MAXNNZ 110000

typedef unsigned long long ull;
typedef __nv_bfloat16 bf16;

// ---------------- device scratch (A basis = [x,h]; B basis = [x,rh]) ----------------
__device__ __align__(16) float g_xkA[BATCH*XKSTR];
__device__ __align__(16) bf16  g_xhA[BATCH*XKSTR];
__device__ __align__(16) bf16  g_xlA[BATCH*XKSTR];
__device__ __align__(16) float g_xkB[BATCH*XKSTR];
__device__ __align__(16) bf16  g_xhB[BATCH*XKSTR];
__device__ __align__(16) bf16  g_xlB[BATCH*XKSTR];
__device__ float g_h0[BATCH*NNODES*UNITS];
__device__ float g_h1[BATCH*NNODES*UNITS];
__device__ float g_u [BATCH*NNODES*UNITS];
__device__ float g_din[BATCH*NNODES];
__device__ int   g_rowptr[NNODES+1];
__device__ int   g_cols[MAXNNZ];
__device__ float g_vals[MAXNNZ];
__device__ unsigned g_wph[8][WPMAX];
__device__ unsigned g_wpl[8][WPMAX];
__device__ unsigned g_pbar[BATCH];

__global__ void init_pbar(){ if (threadIdx.x < BATCH) g_pbar[threadIdx.x] = 0u; }

// ---------------- helpers ----------------
__device__ __forceinline__ void bfsplit(float a, bf16 &h, bf16 &l){
    h = __float2bfloat16(a);
    l = __float2bfloat16(a - __bfloat162float(h));
}
__device__ __forceinline__ void mma16816(float* d, const unsigned* a, const unsigned* b){
    asm volatile("mma.sync.aligned.m16n8k16.row.col.f32.bf16.bf16.f32 "
        "{%0,%1,%2,%3}, {%4,%5,%6,%7}, {%8,%9}, {%0,%1,%2,%3};"
        : "+f"(d[0]), "+f"(d[1]), "+f"(d[2]), "+f"(d[3])
        : "r"(a[0]), "r"(a[1]), "r"(a[2]), "r"(a[3]), "r"(b[0]), "r"(b[1]));
}
// pair barrier, FULL: release + acquire
__device__ __forceinline__ void psync(unsigned* ctr, unsigned &ep){
    __threadfence();
    __syncthreads();
    if (threadIdx.x == 0){
        ep += 2;
        atomicAdd(ctr, 1u);
        while (*(volatile unsigned*)ctr < ep) { }
    }
    __syncthreads();
    __threadfence();
}
// pair barrier, RELEASE-ONLY (R14-proven): no acquire flush; safe when no
// post-barrier read consumes peer-fresh data before the next full psync.
__device__ __forceinline__ void psync_rel(unsigned* ctr, unsigned &ep){
    __threadfence();
    __syncthreads();
    if (threadIdx.x == 0){
        ep += 2;
        atomicAdd(ctr, 1u);
        while (*(volatile unsigned*)ctr < ep) { }
    }
    __syncthreads();
}

// ---------------- setup: compact CSR of S (proven R1) ----------------
__global__ void build_csr(const float* __restrict__ S){
    __shared__ int cnt[NNODES+1];
    int t = threadIdx.x;
    for (int r = t; r < NNODES; r += blockDim.x){
        int c = 0;
        for (int j = 0; j < NNODES; j++) c += (S[r*NNODES + j] != 0.0f);
        cnt[r] = c;
    }
    __syncthreads();
    if (t == 0){
        int acc = 0;
        for (int r = 0; r < NNODES; r++){ int c = cnt[r]; cnt[r] = acc; acc += c; }
        cnt[NNODES] = acc;
    }
    __syncthreads();
    for (int r = t; r <= NNODES; r += blockDim.x) g_rowptr[r] = cnt[r];
    for (int r = t; r < NNODES; r += blockDim.x){
        int p = cnt[r];
        for (int j = 0; j < NNODES; j++){
            float v = S[r*NNODES + j];
            if (v != 0.0f){ g_cols[p] = j; g_vals[p] = v; p++; }
        }
    }
}

// ---------------- setup: folded + frag-packed weights (proven R9) ----------------
__device__ __forceinline__ float wmod(const float* W, int F, int FP, int ONUM, int k, int n){
    int sec = k / FP, col = k - sec*FP;
    if (sec > 2 || col >= F) return 0.f;
    if (sec == 0) return W[col*ONUM + n] - W[(2*F + col)*ONUM + n];
    if (sec == 1) return W[(F + col)*ONUM + n];
    return 2.f*W[(2*F + col)*ONUM + n];
}
__global__ void prep_w(const float* __restrict__ W, int F, int FP, int ONUM, int mat){
    int F3P = 3*FP, NKT = (F3P + 15)/16, NB8 = ONUM/8;
    int total = NB8*NKT*64;
    for (int idx = blockIdx.x*blockDim.x + threadIdx.x; idx < total; idx += gridDim.x*blockDim.x){
        int reg = idx & 1, lane = (idx >> 1) & 31;
        int t2 = idx >> 6; int kt = t2 % NKT, nb8 = t2 / NKT;
        int gg = lane >> 2, qq = lane & 3;
        int n  = nb8*8 + gg;
        int k0 = kt*16 + qq*2 + reg*8;
        float w0 = wmod(W, F, FP, ONUM, k0,     n);
        float w1 = wmod(W, F, FP, ONUM, k0 + 1, n);
        bf16 h0,l0,h1,l1; bfsplit(w0,h0,l0); bfsplit(w1,h1,l1);
        g_wph[mat][idx] = (unsigned)__bfloat16_as_ushort(h0) | ((unsigned)__bfloat16_as_ushort(h1) << 16);
        g_wpl[mat][idx] = (unsigned)__bfloat16_as_ushort(l0) | ((unsigned)__bfloat16_as_ushort(l1) << 16);
    }
}

// ---------------- sparse apply: rows [rbeg,rend), cols [a0,FP); 4-wide unroll ----------------
template<int FP, int STRR, bool WF32>
__device__ void sp_apply(float* xk, bf16* xh, bf16* xl, int src, int dst, int a0,
                         const ull* s_ent, const int* s_rp, int rbeg, int rend)
{
    const int G = (FP - a0) >> 2;
    const int tasks = (rend - rbeg)*G;
    for (int t = threadIdx.x; t < tasks; t += NTH){
        int m = rbeg + t/G, f = a0 + (t - (t/G)*G)*4;
        const float* sp = xk + src + f;
        float ax0=0.f, ay0=0.f, az0=0.f, aw0=0.f;
        float ax1=0.f, ay1=0.f, az1=0.f, aw1=0.f;
        int j = s_rp[m], j1 = s_rp[m+1];
        for (; j + 3 < j1; j += 4){
            ull e0 = s_ent[j],   e1 = s_ent[j+1];
            ull e2 = s_ent[j+2], e3 = s_ent[j+3];
            float v0 = __uint_as_float((unsigned)(e0 >> 32));
            float v1 = __uint_as_float((unsigned)(e1 >> 32));
            float v2 = __uint_as_float((unsigned)(e2 >> 32));
            float v3 = __uint_as_float((unsigned)(e3 >> 32));
            float4 x0 = *(const float4*)(sp + (int)(unsigned)e0 * STRR);
            float4 x1 = *(const float4*)(sp + (int)(unsigned)e1 * STRR);
            float4 x2 = *(const float4*)(sp + (int)(unsigned)e2 * STRR);
            float4 x3 = *(const float4*)(sp + (int)(unsigned)e3 * STRR);
            ax0 += v0*x0.x + v2*x2.x;  ay0 += v0*x0.y + v2*x2.y;
            az0 += v0*x0.z + v2*x2.z;  aw0 += v0*x0.w + v2*x2.w;
            ax1 += v1*x1.x + v3*x3.x;  ay1 += v1*x1.y + v3*x3.y;
            az1 += v1*x1.z + v3*x3.z;  aw1 += v1*x1.w + v3*x3.w;
        }
        for (; j < j1; j++){
            ull e0 = s_ent[j];
            float v0 = __uint_as_float((unsigned)(e0 >> 32));
            float4 x0 = *(const float4*)(sp + (int)(unsigned)e0 * STRR);
            ax0 += v0*x0.x; ay0 += v0*x0.y; az0 += v0*x0.z; aw0 += v0*x0.w;
        }
        float ax = ax0 + ax1, ay = ay0 + ay1, az = az0 + az1, aw = aw0 + aw1;
        int o = m*STRR + dst + f;
        if (WF32) *(float4*)(xk + o) = make_float4(ax, ay, az, aw);
        bf16 hx,lx,hy,ly,hz,lz,hw,lw;
        bfsplit(ax,hx,lx); bfsplit(ay,hy,ly); bfsplit(az,hz,lz); bfsplit(aw,hw,lw);
        uint2 uh, ul2;
        uh.x  = (unsigned)__bfloat16_as_ushort(hx) | ((unsigned)__bfloat16_as_ushort(hy) << 16);
        uh.y  = (unsigned)__bfloat16_as_ushort(hz) | ((unsigned)__bfloat16_as_ushort(hw) << 16);
        ul2.x = (unsigned)__bfloat16_as_ushort(lx) | ((unsigned)__bfloat16_as_ushort(ly) << 16);
        ul2.y = (unsigned)__bfloat16_as_ushort(lz) | ((unsigned)__bfloat16_as_ushort(lw) << 16);
        *(uint2*)(xh + o) = uh;
        *(uint2*)(xl + o) = ul2;
    }
}

// ---------------- barrier-free mma GEMM chunk (direct-LDG A frags; OWN rows only) ----------------
// SPL: per-k-tile A-source select — (kt&7)<4 -> (xh,xl) [x-part, basis A], else (xh2,xl2) [rh, basis B].
// epi 0 (gate): s=sigmoid; n<64 -> rh into B buffers x0[FX+n]; n>=64 -> g_u
// epi 1 (cand): c=tanh; H = u*H + (1-u)*c ; epi 2: epi1 + fused projection
template<int MW, int NW, int ONUM, int FP, int STRR, bool SPL>
__device__ void gemm_chunk(int row0, int rowEnd,
    const bf16* __restrict__ xh, const bf16* __restrict__ xl,
    const bf16* __restrict__ xh2, const bf16* __restrict__ xl2,
    float* xkB, bf16* xhB, bf16* xlB,
    const unsigned* __restrict__ wph, const unsigned* __restrict__ wpl,
    const float* __restrict__ bias, float* H, float* us, int epi, int FX,
    const float* __restrict__ pW, const float* __restrict__ pb,
    float* __restrict__ out_t, float* __restrict__ din, float* s_red)
{
    constexpr int NKT = (3*FP + 15)/16;
    constexpr int NA  = ONUM/(8*NW);
    constexpr int BM  = MW*32;
    const int tid = threadIdx.x, lane = tid & 31, wid = tid >> 5;
    const int mw = wid % MW, nw = wid / MW;
    const int g = lane >> 2, q = lane & 3;

    int aoff[4];
    #pragma unroll
    for (int i = 0; i < 4; i++){
        int r = row0 + mw*32 + i*8 + g;
        if (r > NNODES-1) r = NNODES-1;        // clamp stays within own-rank rows
        aoff[i] = r*STRR + q*2;
    }

    float acc[2][NA][4];
    #pragma unroll
    for (int i = 0; i < 2; i++)
        #pragma unroll
        for (int j = 0; j < NA; j++)
            #pragma unroll
            for (int k = 0; k < 4; k++) acc[i][j][k] = 0.f;

    unsigned aH[2][2][4], aL[2][2][4], bB[2][NA][4];

    auto ldA = [&](int kt, int st){
        int kk = kt*16;
        const bf16* sh = (!SPL || ((kt & 7) < 4)) ? xh : xh2;
        const bf16* sl = (!SPL || ((kt & 7) < 4)) ? xl : xl2;
        #pragma unroll
        for (int ma = 0; ma < 2; ma++){
            aH[st][ma][0] = *(const unsigned*)(sh + aoff[2*ma]   + kk);
            aH[st][ma][1] = *(const unsigned*)(sh + aoff[2*ma+1] + kk);
            aH[st][ma][2] = *(const unsigned*)(sh + aoff[2*ma]   + kk + 8);
            aH[st][ma][3] = *(const unsigned*)(sh + aoff[2*ma+1] + kk + 8);
            aL[st][ma][0] = *(const unsigned*)(sl + aoff[2*ma]   + kk);
            aL[st][ma][1] = *(const unsigned*)(sl + aoff[2*ma+1] + kk);
            aL[st][ma][2] = *(const unsigned*)(sl + aoff[2*ma]   + kk + 8);
            aL[st][ma][3] = *(const unsigned*)(sl + aoff[2*ma+1] + kk + 8);
        }
    };
    auto ldB = [&](int kt, int st){
        #pragma unroll
        for (int na = 0; na < NA; na++){
            int base = (((nw*NA + na)*NKT + kt)*32 + lane)*2;
            uint2 bh = *(const uint2*)(wph + base);
            uint2 bl = *(const uint2*)(wpl + base);
            bB[st][na][0] = bh.x; bB[st][na][1] = bh.y;
            bB[st][na][2] = bl.x; bB[st][na][3] = bl.y;
        }
    };

    ldA(0, 0); ldB(0, 0);
    for (int kt = 0; kt < NKT; kt++){
        int cur = kt & 1, nxt = cur ^ 1;
        if (kt + 1 < NKT){ ldA(kt+1, nxt); ldB(kt+1, nxt); }
        #pragma unroll
        for (int na = 0; na < NA; na++){
            unsigned bh[2] = {bB[cur][na][0], bB[cur][na][1]};
            unsigned bl[2] = {bB[cur][na][2], bB[cur][na][3]};
            #pragma unroll
            for (int ma = 0; ma < 2; ma++){
                mma16816(acc[ma][na], aH[cur][ma], bh);
                mma16816(acc[ma][na], aH[cur][ma], bl);
                mma16816(acc[ma][na], aL[cur][ma], bh);
            }
        }
    }

    float pvp[2][2] = {{0.f,0.f},{0.f,0.f}};
    #pragma unroll
    for (int ma = 0; ma < 2; ma++){
        #pragma unroll
        for (int na = 0; na < NA; na++){
            int n0 = nw*(8*NA) + na*8 + q*2;
            #pragma unroll
            for (int half = 0; half < 2; half++){
                int r = row0 + mw*32 + ma*16 + g + half*8;
                if (r >= rowEnd) continue;
                float v0 = acc[ma][na][half*2 + 0] + bias[n0];
                float v1 = acc[ma][na][half*2 + 1] + bias[n0 + 1];
                if (epi == 0){
                    float s0 = 1.f/(1.f + expf(-v0));
                    float s1 = 1.f/(1.f + expf(-v1));
                    if (n0 < UNITS){
                        float r0 = s0 * H[r*UNITS + n0];
                        float r1 = s1 * H[r*UNITS + n0 + 1];
                        int o = r*STRR + FX + n0;
                        xkB[o] = r0; xkB[o+1] = r1;
                        bf16 h, l;
                        bfsplit(r0, h, l); xhB[o] = h;   xlB[o] = l;
                        bfsplit(r1, h, l); xhB[o+1] = h; xlB[o+1] = l;
                    } else {
                        us[r*UNITS + (n0 - UNITS)]     = s0;
                        us[r*UNITS + (n0 - UNITS) + 1] = s1;
                    }
                } else {
                    float c0 = tanhf(v0), c1 = tanhf(v1);
                    float u0 = us[r*UNITS + n0],     u1 = us[r*UNITS + n0 + 1];
                    float h0v = H[r*UNITS + n0],     h1v = H[r*UNITS + n0 + 1];
                    float hn0 = u0*h0v + (1.f - u0)*c0;
                    float hn1 = u1*h1v + (1.f - u1)*c1;
                    H[r*UNITS + n0]     = hn0;
                    H[r*UNITS + n0 + 1] = hn1;
                    if (epi == 2) pvp[ma][half] += hn0*pW[n0] + hn1*pW[n0 + 1];
                }
            }
        }
    }
    if (epi == 2){
        #pragma unroll
        for (int ma = 0; ma < 2; ma++)
            #pragma unroll
            for (int half = 0; half < 2; half++){
                float v = pvp[ma][half];
                v += __shfl_down_sync(0xffffffffu, v, 2);
                v += __shfl_down_sync(0xffffffffu, v, 1);
                if (q == 0) s_red[(mw*32 + ma*16 + g + half*8)*NW + nw] = v;
            }
        __syncthreads();
        if (tid < BM){
            int r = row0 + tid;
            if (r < rowEnd){
                float v = pb[0];
                #pragma unroll
                for (int w2 = 0; w2 < NW; w2++) v += s_red[tid*NW + w2];
                din[r]  = v;
                out_t[r] = v;
            }
        }
        __syncthreads();
    }
}

// ---------------- one GRU cell (R12 psync structure; SPL = layer-1 x-part reuse) ----------------
template<int FX, int F, int FP, int STRR>
__device__ void cell_run(int b, int rbeg, int rend,
                         const float* __restrict__ xptr, float* H,
                         int matg, int matc,
                         const float* gb, const float* cb, int epi_cand,
                         const float* pW, const float* pb, float* out_t,
                         unsigned* ctr, unsigned &ep,
                         const ull* s_ent, const int* s_rp, float* s_red)
{
    constexpr bool SPL = (FX == UNITS);    // layer-1 cells: cand reads x-part from basis A
    float* xkA = g_xkA + b*XKSTR;  bf16* xhA = g_xhA + b*XKSTR;  bf16* xlA = g_xlA + b*XKSTR;
    float* xkB = g_xkB + b*XKSTR;  bf16* xhB = g_xhB + b*XKSTR;  bf16* xlB = g_xlB + b*XKSTR;
    float* us  = g_u   + b*NNODES*UNITS;
    float* din = g_din + b*NNODES;

    __syncthreads();   // prev-cell H/din (own-CTA cross-warp)
    // concat own rows: A.x0 = [x, h] + pads ; B.x0 x-cols (skipped when SPL)
    for (int idx = threadIdx.x; idx < (rend - rbeg)*FP; idx += NTH){
        int m = rbeg + idx/FP, f = idx - (idx/FP)*FP;
        int o = m*STRR + f;
        float v;
        bf16 h, l;
        if (f >= F){
            xkA[o] = 0.f; xhA[o] = __float2bfloat16(0.f); xlA[o] = __float2bfloat16(0.f);
            if (!SPL){ xkB[o] = 0.f; xhB[o] = __float2bfloat16(0.f); xlB[o] = __float2bfloat16(0.f); }
            continue;
        }
        if (f < FX){
            v = (FX == 2) ? xptr[m*DIN + f] : ((FX == 1) ? xptr[m] : xptr[m*UNITS + f]);
            bfsplit(v, h, l);
            xkA[o] = v; xhA[o] = h; xlA[o] = l;
            if (!SPL){ xkB[o] = v; xhB[o] = h; xlB[o] = l; }
        } else {
            v = H[m*UNITS + (f - FX)];
            bfsplit(v, h, l);
            xkA[o] = v; xhA[o] = h; xlA[o] = l;
        }
    }
    psync(ctr, ep);                                                    // (a) x0 all rows ready
    sp_apply<FP,STRR,true >(xkA, xhA, xlA, 0,  FP,   0, s_ent, s_rp, rbeg, rend);  // A: S x0
    psync(ctr, ep);                                                    // (b) x1 all rows ready
    sp_apply<FP,STRR,false>(xkA, xhA, xlA, FP, 2*FP, 0, s_ent, s_rp, rbeg, rend);  // A: S x1
    __syncthreads();                                                   // own rows only below
    gemm_chunk<4,4,128,FP,STRR,false>(rbeg,       rend, xhA, xlA, xhA, xlA, xkB, xhB, xlB,
        g_wph[matg], g_wpl[matg], gb, H, us, 0, FX, nullptr, nullptr, nullptr, din, s_red);
    gemm_chunk<2,8,128,FP,STRR,false>(rbeg + 128, rend, xhA, xlA, xhA, xlA, xkB, xhB, xlB,
        g_wph[matg], g_wpl[matg], gb, H, us, 0, FX, nullptr, nullptr, nullptr, din, s_red);
    psync(ctr, ep);                                                    // (c) B.x0 (rh) all rows
    {
        const int a0 = SPL ? UNITS : 0;       // SPL: rh cols only (x-part served by A)
        sp_apply<FP,STRR,true >(xkB, xhB, xlB, 0,  FP,   a0, s_ent, s_rp, rbeg, rend);
        psync(ctr, ep);                                                // (d) B.x1 all rows
        sp_apply<FP,STRR,false>(xkB, xhB, xlB, FP, 2*FP, a0, s_ent, s_rp, rbeg, rend);
    }
    __syncthreads();                                                   // own rows only below
    if (SPL){
        gemm_chunk<4,4,64,FP,STRR,true >(rbeg,       rend, xhA, xlA, xhB, xlB, xkB, xhB, xlB,
            g_wph[matc], g_wpl[matc], cb, H, us, epi_cand, FX, pW, pb, out_t, din, s_red);
        gemm_chunk<2,8,64,FP,STRR,true >(rbeg + 128, rend, xhA, xlA, xhB, xlB, xkB, xhB, xlB,
            g_wph[matc], g_wpl[matc], cb, H, us, epi_cand, FX, pW, pb, out_t, din, s_red);
    } else {
        gemm_chunk<4,4,64,FP,STRR,false>(rbeg,       rend, xhB, xlB, xhB, xlB, xkB, xhB, xlB,
            g_wph[matc], g_wpl[matc], cb, H, us, epi_cand, FX, pW, pb, out_t, din, s_red);
        gemm_chunk<2,8,64,FP,STRR,false>(rbeg + 128, rend, xhB, xlB, xhB, xlB, xkB, xhB, xlB,
            g_wph[matc], g_wpl[matc], cb, H, us, epi_cand, FX, pW, pb, out_t, din, s_red);
    }
    psync_rel(ctr, ep);    // (e) cell end: anti-dependence across stride flip only
}

// ---------------- the whole network: 2 CTAs per batch (node split at 192) ----------------
__global__ void __launch_bounds__(NTH, 1)
dcrnn_pair(const float* __restrict__ inputs,
           const float* e0gb, const float* e0cb,
           const float* e1gb, const float* e1cb,
           const float* d0gb, const float* d0cb,
           const float* d1gb, const float* d1cb,
           const float* pW, const float* pb, float* __restrict__ out)
{
    __shared__ ull s_ent[MAXE];
    __shared__ int s_rp[NNODES+1];
    __shared__ float s_red[128*8];

    const int b = blockIdx.x >> 1, rank = blockIdx.x & 1;
    const int rbeg = rank ? SPLIT : 0;
    const int rend = rank ? NNODES : SPLIT;
    const int tid = threadIdx.x;
    unsigned* ctr = &g_pbar[b];
    unsigned ep = 0;

    // CSR -> smem
    int nnz = g_rowptr[NNODES]; if (nnz > MAXE) nnz = MAXE;
    for (int j = tid; j < nnz; j += NTH)
        s_ent[j] = ((ull)__float_as_uint(g_vals[j]) << 32) | (unsigned)g_cols[j];
    for (int r = tid; r <= NNODES; r += NTH)
        s_rp[r] = (g_rowptr[r] > MAXE) ? MAXE : g_rowptr[r];
    // zero own state
    float* h0  = g_h0 + b*NNODES*UNITS;
    float* h1  = g_h1 + b*NNODES*UNITS;
    float* din = g_din + b*NNODES;
    for (int i = tid; i < (rend - rbeg)*UNITS; i += NTH)
        { h0[rbeg*UNITS + i] = 0.f; h1[rbeg*UNITS + i] = 0.f; }
    for (int i = tid; i < rend - rbeg; i += NTH) din[rbeg + i] = 0.f;

    // ---- encoder ----
    for (int t = 0; t < TSTEPS; t++){
        const float* xin = inputs + ((size_t)t*BATCH + b)*NNODES*DIN;
        cell_run<2,66,68,208>(b, rbeg, rend, xin, h0, 0, 4, e0gb, e0cb, 1,
                              nullptr, nullptr, nullptr, ctr, ep, s_ent, s_rp, s_red);
        cell_run<64,128,128,384>(b, rbeg, rend, h0, h1, 1, 5, e1gb, e1cb, 1,
                              nullptr, nullptr, nullptr, ctr, ep, s_ent, s_rp, s_red);
    }
    // ---- decoder ----
    for (int t = 0; t < HORIZON; t++){
        cell_run<1,65,68,208>(b, rbeg, rend, din, h0, 2, 6, d0gb, d0cb, 1,
                              nullptr, nullptr, nullptr, ctr, ep, s_ent, s_rp, s_red);
        cell_run<64,128,128,384>(b, rbeg, rend, h0, h1, 3, 7, d1gb, d1cb, 2,
                              pW, pb, out + ((size_t)t*BATCH + b)*NNODES,
                              ctr, ep, s_ent, s_rp, s_red);
    }
}

extern "C" void kernel_launch(void* const* d_in, const int* in_sizes, int n_in,
                              void* d_out, int out_size)
{
    const float* inputs  = (const float*)d_in[0];
    const float* support = (const float*)d_in[1];
    const float* e0gW = (const float*)d_in[2];  const float* e0gb = (const float*)d_in[3];
    const float* e0cW = (const float*)d_in[4];  const float* e0cb = (const float*)d_in[5];
    const float* e1gW = (const float*)d_in[6];  const float* e1gb = (const float*)d_in[7];
    const float* e1cW = (const float*)d_in[8];  const float* e1cb = (const float*)d_in[9];
    const float* d0gW = (const float*)d_in[10]; const float* d0gb = (const float*)d_in[11];
    const float* d0cW = (const float*)d_in[12]; const float* d0cb = (const float*)d_in[13];
    const float* d1gW = (const float*)d_in[14]; const float* d1gb = (const float*)d_in[15];
    const float* d1cW = (const float*)d_in[16]; const float* d1cb = (const float*)d_in[17];
    const float* pW   = (const float*)d_in[18]; const float* pb   = (const float*)d_in[19];
    float* out = (float*)d_out;

    init_pbar<<<1, BATCH>>>();
    build_csr<<<1, 352>>>(support);
    // fold + frag-pack weights: gate mats 0..3, cand mats 4..7
    prep_w<<<48, 256>>>(e0gW, 66, 68, 128, 0);
    prep_w<<<48, 256>>>(e1gW, 128, 128, 128, 1);
    prep_w<<<48, 256>>>(d0gW, 65, 68, 128, 2);
    prep_w<<<48, 256>>>(d1gW, 128, 128, 128, 3);
    prep_w<<<48, 256>>>(e0cW, 66, 68, 64, 4);
    prep_w<<<48, 256>>>(e1cW, 128, 128, 64, 5);
    prep_w<<<48, 256>>>(d0cW, 65, 68, 64, 6);
    prep_w<<<48, 256>>>(d1cW, 128, 128, 64, 7);

    dcrnn_pair<<<2*BATCH, NTH>>>(inputs,
        e0gb, e0cb, e1gb, e1cb, d0gb, d0cb, d1gb, d1cb,
        pW, pb, out);
}

// round 16
// speedup vs baseline: 1.1061x; 1.0099x over previous
#include <cuda_runtime.h>
#include <cuda_bf16.h>
#include <math.h>

// ---------------- problem constants ----------------
#define NNODES 325
#define BATCH  64
#define TSTEPS 12
#define HORIZON 12
#define UNITS  64
#define DIN    2
#define XKSTR  (NNODES*384)
#define NTH    512
#define SPLIT  192               // rank0 rows [0,192) (=128+64 exact), rank1 [192,325)
#define MAXE   2600
#define WPMAX  32768
#define MAXNNZ 110000

typedef unsigned long long ull;
typedef __nv_bfloat16 bf16;

// ---------------- device scratch (A basis = [x,h]; B basis = [x,rh]) ----------------
__device__ __align__(16) float g_xkA[BATCH*XKSTR];
__device__ __align__(16) bf16  g_xhA[BATCH*XKSTR];
__device__ __align__(16) bf16  g_xlA[BATCH*XKSTR];
__device__ __align__(16) float g_xkB[BATCH*XKSTR];
__device__ __align__(16) bf16  g_xhB[BATCH*XKSTR];
__device__ __align__(16) bf16  g_xlB[BATCH*XKSTR];
__device__ float g_h0[BATCH*NNODES*UNITS];
__device__ float g_h1[BATCH*NNODES*UNITS];
__device__ float g_u [BATCH*NNODES*UNITS];
__device__ float g_din[BATCH*NNODES];
__device__ int   g_rowptr[NNODES+1];
__device__ int   g_cols[MAXNNZ];
__device__ float g_vals[MAXNNZ];
__device__ unsigned g_wph[8][WPMAX];
__device__ unsigned g_wpl[8][WPMAX];
__device__ unsigned g_pbar[BATCH];

// ---------------- helpers ----------------
__device__ __forceinline__ void bfsplit(float a, bf16 &h, bf16 &l){
    h = __float2bfloat16(a);
    l = __float2bfloat16(a - __bfloat162float(h));
}
__device__ __forceinline__ void mma16816(float* d, const unsigned* a, const unsigned* b){
    asm volatile("mma.sync.aligned.m16n8k16.row.col.f32.bf16.bf16.f32 "
        "{%0,%1,%2,%3}, {%4,%5,%6,%7}, {%8,%9}, {%0,%1,%2,%3};"
        : "+f"(d[0]), "+f"(d[1]), "+f"(d[2]), "+f"(d[3])
        : "r"(a[0]), "r"(a[1]), "r"(a[2]), "r"(a[3]), "r"(b[0]), "r"(b[1]));
}
// pair barrier, FULL: release + acquire (R12-proven)
__device__ __forceinline__ void psync(unsigned* ctr, unsigned &ep){
    __threadfence();
    __syncthreads();
    if (threadIdx.x == 0){
        ep += 2;
        atomicAdd(ctr, 1u);
        while (*(volatile unsigned*)ctr < ep) { }
    }
    __syncthreads();
    __threadfence();
}

// ---------------- setup kernel 1: pair barriers + compact CSR of S ----------------
__global__ void setup_all(const float* __restrict__ S){
    __shared__ int cnt[NNODES+1];
    int t = threadIdx.x;
    if (t < BATCH) g_pbar[t] = 0u;
    for (int r = t; r < NNODES; r += blockDim.x){
        int c = 0;
        for (int j = 0; j < NNODES; j++) c += (S[r*NNODES + j] != 0.0f);
        cnt[r] = c;
    }
    __syncthreads();
    if (t == 0){
        int acc = 0;
        for (int r = 0; r < NNODES; r++){ int c = cnt[r]; cnt[r] = acc; acc += c; }
        cnt[NNODES] = acc;
    }
    __syncthreads();
    for (int r = t; r <= NNODES; r += blockDim.x) g_rowptr[r] = cnt[r];
    for (int r = t; r < NNODES; r += blockDim.x){
        int p = cnt[r];
        for (int j = 0; j < NNODES; j++){
            float v = S[r*NNODES + j];
            if (v != 0.0f){ g_cols[p] = j; g_vals[p] = v; p++; }
        }
    }
}

// ---------------- setup kernel 2: fold + frag-pack ALL 8 weight matrices ----------------
__device__ __forceinline__ float wmod(const float* W, int F, int FP, int ONUM, int k, int n){
    int sec = k / FP, col = k - sec*FP;
    if (sec > 2 || col >= F) return 0.f;
    if (sec == 0) return W[col*ONUM + n] - W[(2*F + col)*ONUM + n];
    if (sec == 1) return W[(F + col)*ONUM + n];
    return 2.f*W[(2*F + col)*ONUM + n];
}
__global__ void prep_all(const float* W0, const float* W1, const float* W2, const float* W3,
                         const float* W4, const float* W5, const float* W6, const float* W7)
{
    const float* Ws[8] = {W0, W1, W2, W3, W4, W5, W6, W7};
    const int Fs[8]  = {66, 128, 65, 128, 66, 128, 65, 128};
    const int FPs[8] = {68, 128, 68, 128, 68, 128, 68, 128};
    const int ONs[8] = {128, 128, 128, 128, 64, 64, 64, 64};
    for (int mat = 0; mat < 8; mat++){
        const float* W = Ws[mat];
        int F = Fs[mat], FP = FPs[mat], ONUM = ONs[mat];
        int F3P = 3*FP, NKT = (F3P + 15)/16, NB8 = ONUM/8;
        int total = NB8*NKT*64;
        for (int idx = blockIdx.x*blockDim.x + threadIdx.x; idx < total;
             idx += gridDim.x*blockDim.x){
            int reg = idx & 1, lane = (idx >> 1) & 31;
            int t2 = idx >> 6; int kt = t2 % NKT, nb8 = t2 / NKT;
            int gg = lane >> 2, qq = lane & 3;
            int n  = nb8*8 + gg;
            int k0 = kt*16 + qq*2 + reg*8;
            float w0 = wmod(W, F, FP, ONUM, k0,     n);
            float w1 = wmod(W, F, FP, ONUM, k0 + 1, n);
            bf16 h0,l0,h1,l1; bfsplit(w0,h0,l0); bfsplit(w1,h1,l1);
            g_wph[mat][idx] = (unsigned)__bfloat16_as_ushort(h0) | ((unsigned)__bfloat16_as_ushort(h1) << 16);
            g_wpl[mat][idx] = (unsigned)__bfloat16_as_ushort(l0) | ((unsigned)__bfloat16_as_ushort(l1) << 16);
        }
    }
}

// ---------------- sparse apply: rows [rbeg,rend), cols [a0,FP); R12 2-wide loop ----------------
template<int FP, int STRR, bool WF32>
__device__ void sp_apply(float* xk, bf16* xh, bf16* xl, int src, int dst, int a0,
                         const ull* s_ent, const int* s_rp, int rbeg, int rend)
{
    const int G = (FP - a0) >> 2;
    const int tasks = (rend - rbeg)*G;
    for (int t = threadIdx.x; t < tasks; t += NTH){
        int m = rbeg + t/G, f = a0 + (t - (t/G)*G)*4;
        const float* sp = xk + src + f;
        float ax = 0.f, ay = 0.f, az = 0.f, aw = 0.f;
        int j = s_rp[m], j1 = s_rp[m+1];
        for (; j + 1 < j1; j += 2){
            ull e0 = s_ent[j], e1 = s_ent[j+1];
            float v0 = __uint_as_float((unsigned)(e0 >> 32));
            float v1 = __uint_as_float((unsigned)(e1 >> 32));
            float4 x0 = *(const float4*)(sp + (int)(unsigned)e0 * STRR);
            float4 x1 = *(const float4*)(sp + (int)(unsigned)e1 * STRR);
            ax += v0*x0.x + v1*x1.x;  ay += v0*x0.y + v1*x1.y;
            az += v0*x0.z + v1*x1.z;  aw += v0*x0.w + v1*x1.w;
        }
        if (j < j1){
            ull e0 = s_ent[j];
            float v0 = __uint_as_float((unsigned)(e0 >> 32));
            float4 x0 = *(const float4*)(sp + (int)(unsigned)e0 * STRR);
            ax += v0*x0.x; ay += v0*x0.y; az += v0*x0.z; aw += v0*x0.w;
        }
        int o = m*STRR + dst + f;
        if (WF32) *(float4*)(xk + o) = make_float4(ax, ay, az, aw);
        bf16 hx,lx,hy,ly,hz,lz,hw,lw;
        bfsplit(ax,hx,lx); bfsplit(ay,hy,ly); bfsplit(az,hz,lz); bfsplit(aw,hw,lw);
        uint2 uh, ul2;
        uh.x  = (unsigned)__bfloat16_as_ushort(hx) | ((unsigned)__bfloat16_as_ushort(hy) << 16);
        uh.y  = (unsigned)__bfloat16_as_ushort(hz) | ((unsigned)__bfloat16_as_ushort(hw) << 16);
        ul2.x = (unsigned)__bfloat16_as_ushort(lx) | ((unsigned)__bfloat16_as_ushort(ly) << 16);
        ul2.y = (unsigned)__bfloat16_as_ushort(lz) | ((unsigned)__bfloat16_as_ushort(lw) << 16);
        *(uint2*)(xh + o) = uh;
        *(uint2*)(xl + o) = ul2;
    }
}

// ---------------- barrier-free mma GEMM chunk (direct-LDG A frags; OWN rows only) ----------------
// SPL: per-k-tile A-source select — (kt&7)<4 -> (xh,xl) [x-part, basis A], else (xh2,xl2) [rh, basis B]
template<int MW, int NW, int ONUM, int FP, int STRR, bool SPL>
__device__ void gemm_chunk(int row0, int rowEnd,
    const bf16* __restrict__ xh, const bf16* __restrict__ xl,
    const bf16* __restrict__ xh2, const bf16* __restrict__ xl2,
    float* xkB, bf16* xhB, bf16* xlB,
    const unsigned* __restrict__ wph, const unsigned* __restrict__ wpl,
    const float* __restrict__ bias, float* H, float* us, int epi, int FX,
    const float* __restrict__ pW, const float* __restrict__ pb,
    float* __restrict__ out_t, float* __restrict__ din, float* s_red)
{
    constexpr int NKT = (3*FP + 15)/16;
    constexpr int NA  = ONUM/(8*NW);
    constexpr int BM  = MW*32;
    const int tid = threadIdx.x, lane = tid & 31, wid = tid >> 5;
    const int mw = wid % MW, nw = wid / MW;
    const int g = lane >> 2, q = lane & 3;

    int aoff[4];
    #pragma unroll
    for (int i = 0; i < 4; i++){
        int r = row0 + mw*32 + i*8 + g;
        if (r > NNODES-1) r = NNODES-1;        // clamp stays within own-rank rows
        aoff[i] = r*STRR + q*2;
    }

    float acc[2][NA][4];
    #pragma unroll
    for (int i = 0; i < 2; i++)
        #pragma unroll
        for (int j = 0; j < NA; j++)
            #pragma unroll
            for (int k = 0; k < 4; k++) acc[i][j][k] = 0.f;

    unsigned aH[2][2][4], aL[2][2][4], bB[2][NA][4];

    auto ldA = [&](int kt, int st){
        int kk = kt*16;
        const bf16* sh = (!SPL || ((kt & 7) < 4)) ? xh : xh2;
        const bf16* sl = (!SPL || ((kt & 7) < 4)) ? xl : xl2;
        #pragma unroll
        for (int ma = 0; ma < 2; ma++){
            aH[st][ma][0] = *(const unsigned*)(sh + aoff[2*ma]   + kk);
            aH[st][ma][1] = *(const unsigned*)(sh + aoff[2*ma+1] + kk);
            aH[st][ma][2] = *(const unsigned*)(sh + aoff[2*ma]   + kk + 8);
            aH[st][ma][3] = *(const unsigned*)(sh + aoff[2*ma+1] + kk + 8);
            aL[st][ma][0] = *(const unsigned*)(sl + aoff[2*ma]   + kk);
            aL[st][ma][1] = *(const unsigned*)(sl + aoff[2*ma+1] + kk);
            aL[st][ma][2] = *(const unsigned*)(sl + aoff[2*ma]   + kk + 8);
            aL[st][ma][3] = *(const unsigned*)(sl + aoff[2*ma+1] + kk + 8);
        }
    };
    auto ldB = [&](int kt, int st){
        #pragma unroll
        for (int na = 0; na < NA; na++){
            int base = (((nw*NA + na)*NKT + kt)*32 + lane)*2;
            uint2 bh = *(const uint2*)(wph + base);
            uint2 bl = *(const uint2*)(wpl + base);
            bB[st][na][0] = bh.x; bB[st][na][1] = bh.y;
            bB[st][na][2] = bl.x; bB[st][na][3] = bl.y;
        }
    };

    ldA(0, 0); ldB(0, 0);
    for (int kt = 0; kt < NKT; kt++){
        int cur = kt & 1, nxt = cur ^ 1;
        if (kt + 1 < NKT){ ldA(kt+1, nxt); ldB(kt+1, nxt); }
        #pragma unroll
        for (int na = 0; na < NA; na++){
            unsigned bh[2] = {bB[cur][na][0], bB[cur][na][1]};
            unsigned bl[2] = {bB[cur][na][2], bB[cur][na][3]};
            #pragma unroll
            for (int ma = 0; ma < 2; ma++){
                mma16816(acc[ma][na], aH[cur][ma], bh);
                mma16816(acc[ma][na], aH[cur][ma], bl);
                mma16816(acc[ma][na], aL[cur][ma], bh);
            }
        }
    }

    float pvp[2][2] = {{0.f,0.f},{0.f,0.f}};
    #pragma unroll
    for (int ma = 0; ma < 2; ma++){
        #pragma unroll
        for (int na = 0; na < NA; na++){
            int n0 = nw*(8*NA) + na*8 + q*2;
            #pragma unroll
            for (int half = 0; half < 2; half++){
                int r = row0 + mw*32 + ma*16 + g + half*8;
                if (r >= rowEnd) continue;
                float v0 = acc[ma][na][half*2 + 0] + bias[n0];
                float v1 = acc[ma][na][half*2 + 1] + bias[n0 + 1];
                if (epi == 0){
                    float s0 = 1.f/(1.f + expf(-v0));
                    float s1 = 1.f/(1.f + expf(-v1));
                    if (n0 < UNITS){
                        float r0 = s0 * H[r*UNITS + n0];
                        float r1 = s1 * H[r*UNITS + n0 + 1];
                        int o = r*STRR + FX + n0;
                        xkB[o] = r0; xkB[o+1] = r1;
                        bf16 h, l;
                        bfsplit(r0, h, l); xhB[o] = h;   xlB[o] = l;
                        bfsplit(r1, h, l); xhB[o+1] = h; xlB[o+1] = l;
                    } else {
                        us[r*UNITS + (n0 - UNITS)]     = s0;
                        us[r*UNITS + (n0 - UNITS) + 1] = s1;
                    }
                } else {
                    float c0 = tanhf(v0), c1 = tanhf(v1);
                    float u0 = us[r*UNITS + n0],     u1 = us[r*UNITS + n0 + 1];
                    float h0v = H[r*UNITS + n0],     h1v = H[r*UNITS + n0 + 1];
                    float hn0 = u0*h0v + (1.f - u0)*c0;
                    float hn1 = u1*h1v + (1.f - u1)*c1;
                    H[r*UNITS + n0]     = hn0;
                    H[r*UNITS + n0 + 1] = hn1;
                    if (epi == 2) pvp[ma][half] += hn0*pW[n0] + hn1*pW[n0 + 1];
                }
            }
        }
    }
    if (epi == 2){
        #pragma unroll
        for (int ma = 0; ma < 2; ma++)
            #pragma unroll
            for (int half = 0; half < 2; half++){
                float v = pvp[ma][half];
                v += __shfl_down_sync(0xffffffffu, v, 2);
                v += __shfl_down_sync(0xffffffffu, v, 1);
                if (q == 0) s_red[(mw*32 + ma*16 + g + half*8)*NW + nw] = v;
            }
        __syncthreads();
        if (tid < BM){
            int r = row0 + tid;
            if (r < rowEnd){
                float v = pb[0];
                #pragma unroll
                for (int w2 = 0; w2 < NW; w2++) v += s_red[tid*NW + w2];
                din[r]  = v;
                out_t[r] = v;
            }
        }
        __syncthreads();
    }
}

// ---------------- one GRU cell (R12 psync structure; SPL = layer-1 x-part reuse) ----------------
template<int FX, int F, int FP, int STRR>
__device__ void cell_run(int b, int rbeg, int rend,
                         const float* __restrict__ xptr, float* H,
                         int matg, int matc,
                         const float* gb, const float* cb, int epi_cand,
                         const float* pW, const float* pb, float* out_t,
                         unsigned* ctr, unsigned &ep,
                         const ull* s_ent, const int* s_rp, float* s_red)
{
    constexpr bool SPL = (FX == UNITS);    // layer-1 cells: cand reads x-part from basis A
    float* xkA = g_xkA + b*XKSTR;  bf16* xhA = g_xhA + b*XKSTR;  bf16* xlA = g_xlA + b*XKSTR;
    float* xkB = g_xkB + b*XKSTR;  bf16* xhB = g_xhB + b*XKSTR;  bf16* xlB = g_xlB + b*XKSTR;
    float* us  = g_u   + b*NNODES*UNITS;
    float* din = g_din + b*NNODES;

    __syncthreads();   // prev-cell H/din (own-CTA cross-warp)
    // concat own rows: A.x0 = [x, h] + pads ; B.x0 x-cols (skipped when SPL)
    for (int idx = threadIdx.x; idx < (rend - rbeg)*FP; idx += NTH){
        int m = rbeg + idx/FP, f = idx - (idx/FP)*FP;
        int o = m*STRR + f;
        float v;
        bf16 h, l;
        if (f >= F){
            xkA[o] = 0.f; xhA[o] = __float2bfloat16(0.f); xlA[o] = __float2bfloat16(0.f);
            if (!SPL){ xkB[o] = 0.f; xhB[o] = __float2bfloat16(0.f); xlB[o] = __float2bfloat16(0.f); }
            continue;
        }
        if (f < FX){
            v = (FX == 2) ? xptr[m*DIN + f] : ((FX == 1) ? xptr[m] : xptr[m*UNITS + f]);
            bfsplit(v, h, l);
            xkA[o] = v; xhA[o] = h; xlA[o] = l;
            if (!SPL){ xkB[o] = v; xhB[o] = h; xlB[o] = l; }
        } else {
            v = H[m*UNITS + (f - FX)];
            bfsplit(v, h, l);
            xkA[o] = v; xhA[o] = h; xlA[o] = l;
        }
    }
    psync(ctr, ep);                                                    // (a) x0 all rows ready
    sp_apply<FP,STRR,true >(xkA, xhA, xlA, 0,  FP,   0, s_ent, s_rp, rbeg, rend);  // A: S x0
    psync(ctr, ep);                                                    // (b) x1 all rows ready
    sp_apply<FP,STRR,false>(xkA, xhA, xlA, FP, 2*FP, 0, s_ent, s_rp, rbeg, rend);  // A: S x1
    __syncthreads();                                                   // own rows only below
    gemm_chunk<4,4,128,FP,STRR,false>(rbeg,       rend, xhA, xlA, xhA, xlA, xkB, xhB, xlB,
        g_wph[matg], g_wpl[matg], gb, H, us, 0, FX, nullptr, nullptr, nullptr, din, s_red);
    gemm_chunk<2,8,128,FP,STRR,false>(rbeg + 128, rend, xhA, xlA, xhA, xlA, xkB, xhB, xlB,
        g_wph[matg], g_wpl[matg], gb, H, us, 0, FX, nullptr, nullptr, nullptr, din, s_red);
    psync(ctr, ep);                                                    // (c) B.x0 (rh) all rows
    {
        const int a0 = SPL ? UNITS : 0;       // SPL: rh cols only (x-part served by A)
        sp_apply<FP,STRR,true >(xkB, xhB, xlB, 0,  FP,   a0, s_ent, s_rp, rbeg, rend);
        psync(ctr, ep);                                                // (d) B.x1 all rows
        sp_apply<FP,STRR,false>(xkB, xhB, xlB, FP, 2*FP, a0, s_ent, s_rp, rbeg, rend);
    }
    __syncthreads();                                                   // own rows only below
    if (SPL){
        gemm_chunk<4,4,64,FP,STRR,true >(rbeg,       rend, xhA, xlA, xhB, xlB, xkB, xhB, xlB,
            g_wph[matc], g_wpl[matc], cb, H, us, epi_cand, FX, pW, pb, out_t, din, s_red);
        gemm_chunk<2,8,64,FP,STRR,true >(rbeg + 128, rend, xhA, xlA, xhB, xlB, xkB, xhB, xlB,
            g_wph[matc], g_wpl[matc], cb, H, us, epi_cand, FX, pW, pb, out_t, din, s_red);
    } else {
        gemm_chunk<4,4,64,FP,STRR,false>(rbeg,       rend, xhB, xlB, xhB, xlB, xkB, xhB, xlB,
            g_wph[matc], g_wpl[matc], cb, H, us, epi_cand, FX, pW, pb, out_t, din, s_red);
        gemm_chunk<2,8,64,FP,STRR,false>(rbeg + 128, rend, xhB, xlB, xhB, xlB, xkB, xhB, xlB,
            g_wph[matc], g_wpl[matc], cb, H, us, epi_cand, FX, pW, pb, out_t, din, s_red);
    }
    psync(ctr, ep);          // (e) CELL END: full psync (R12-proven) across stride flip
}

// ---------------- the whole network: 2 CTAs per batch (node split at 192) ----------------
__global__ void __launch_bounds__(NTH, 1)
dcrnn_pair(const float* __restrict__ inputs,
           const float* e0gb, const float* e0cb,
           const float* e1gb, const float* e1cb,
           const float* d0gb, const float* d0cb,
           const float* d1gb, const float* d1cb,
           const float* pW, const float* pb, float* __restrict__ out)
{
    __shared__ ull s_ent[MAXE];
    __shared__ int s_rp[NNODES+1];
    __shared__ float s_red[128*8];

    const int b = blockIdx.x >> 1, rank = blockIdx.x & 1;
    const int rbeg = rank ? SPLIT : 0;
    const int rend = rank ? NNODES : SPLIT;
    const int tid = threadIdx.x;
    unsigned* ctr = &g_pbar[b];
    unsigned ep = 0;

    // CSR -> smem
    int nnz = g_rowptr[NNODES]; if (nnz > MAXE) nnz = MAXE;
    for (int j = tid; j < nnz; j += NTH)
        s_ent[j] = ((ull)__float_as_uint(g_vals[j]) << 32) | (unsigned)g_cols[j];
    for (int r = tid; r <= NNODES; r += NTH)
        s_rp[r] = (g_rowptr[r] > MAXE) ? MAXE : g_rowptr[r];
    // zero own state
    float* h0  = g_h0 + b*NNODES*UNITS;
    float* h1  = g_h1 + b*NNODES*UNITS;
    float* din = g_din + b*NNODES;
    for (int i = tid; i < (rend - rbeg)*UNITS; i += NTH)
        { h0[rbeg*UNITS + i] = 0.f; h1[rbeg*UNITS + i] = 0.f; }
    for (int i = tid; i < rend - rbeg; i += NTH) din[rbeg + i] = 0.f;

    // ---- encoder ----
    for (int t = 0; t < TSTEPS; t++){
        const float* xin = inputs + ((size_t)t*BATCH + b)*NNODES*DIN;
        cell_run<2,66,68,208>(b, rbeg, rend, xin, h0, 0, 4, e0gb, e0cb, 1,
                              nullptr, nullptr, nullptr, ctr, ep, s_ent, s_rp, s_red);
        cell_run<64,128,128,384>(b, rbeg, rend, h0, h1, 1, 5, e1gb, e1cb, 1,
                              nullptr, nullptr, nullptr, ctr, ep, s_ent, s_rp, s_red);
    }
    // ---- decoder ----
    for (int t = 0; t < HORIZON; t++){
        cell_run<1,65,68,208>(b, rbeg, rend, din, h0, 2, 6, d0gb, d0cb, 1,
                              nullptr, nullptr, nullptr, ctr, ep, s_ent, s_rp, s_red);
        cell_run<64,128,128,384>(b, rbeg, rend, h0, h1, 3, 7, d1gb, d1cb, 2,
                              pW, pb, out + ((size_t)t*BATCH + b)*NNODES,
                              ctr, ep, s_ent, s_rp, s_red);
    }
}

extern "C" void kernel_launch(void* const* d_in, const int* in_sizes, int n_in,
                              void* d_out, int out_size)
{
    const float* inputs  = (const float*)d_in[0];
    const float* support = (const float*)d_in[1];
    const float* e0gW = (const float*)d_in[2];  const float* e0gb = (const float*)d_in[3];
    const float* e0cW = (const float*)d_in[4];  const float* e0cb = (const float*)d_in[5];
    const float* e1gW = (const float*)d_in[6];  const float* e1gb = (const float*)d_in[7];
    const float* e1cW = (const float*)d_in[8];  const float* e1cb = (const float*)d_in[9];
    const float* d0gW = (const float*)d_in[10]; const float* d0gb = (const float*)d_in[11];
    const float* d0cW = (const float*)d_in[12]; const float* d0cb = (const float*)d_in[13];
    const float* d1gW = (const float*)d_in[14]; const float* d1gb = (const float*)d_in[15];
    const float* d1cW = (const float*)d_in[16]; const float* d1cb = (const float*)d_in[17];
    const float* pW   = (const float*)d_in[18]; const float* pb   = (const float*)d_in[19];
    float* out = (float*)d_out;

    // Exactly 3 launches per call: launch idx 5 (= 2nd call's dcrnn_pair) is what
    // ncu -s 5 -c 1 captures -> main-kernel profile instead of setup kernels.
    setup_all<<<1, 352>>>(support);
    prep_all<<<128, 256>>>(e0gW, e1gW, d0gW, d1gW, e0cW, e1cW, d0cW, d1cW);
    dcrnn_pair<<<2*BATCH, NTH>>>(inputs,
        e0gb, e0cb, e1gb, e1cb, d0gb, d0cb, d1gb, d1cb,
        pW, pb, out);
}